// round 6
// baseline (speedup 1.0000x reference)
#include <cuda_runtime.h>
#include <math.h>

#define NLAYERS 4
#define DMODEL 1024
#define NHEADS 16
#define HDIM 64
#define FFDIM 4096
#define BATCH 2
#define SEQ 1024
#define MROWS (BATCH*SEQ)   // 2048

// ---------------- scratch (no allocations allowed) ----------------
__device__ float g_x [(size_t)MROWS*DMODEL];
__device__ float g_nb[(size_t)MROWS*DMODEL];
__device__ float g_qb[(size_t)MROWS*DMODEL];
__device__ float g_kb[(size_t)MROWS*DMODEL];
__device__ float g_vb[(size_t)MROWS*DMODEL];
__device__ float g_ab[(size_t)MROWS*DMODEL];
__device__ float g_sb[(size_t)BATCH*NHEADS*SEQ*SEQ];   // 128 MB scores
__device__ float g_t0b[(size_t)MROWS*FFDIM];
__device__ float g_t1b[(size_t)MROWS*FFDIM];
__device__ float g_biasb[NHEADS*SEQ];

// ---------------- small utility kernels ----------------
__global__ void copy4_k(const float* __restrict__ src, float* __restrict__ dst, int n4) {
    int i = blockIdx.x * blockDim.x + threadIdx.x;
    if (i < n4) ((float4*)dst)[i] = ((const float4*)src)[i];
}

// bias table: tab[h*SEQ + delta] = rel_emb[bucket(delta)][h], delta = max(i-j,0)
__global__ void biastab_k(const float* __restrict__ emb, float* __restrict__ tab) {
    int idx = blockIdx.x * blockDim.x + threadIdx.x;
    if (idx >= NHEADS * SEQ) return;
    int h = idx / SEQ;
    int d = idx % SEQ;
    int bucket;
    if (d < 16) {
        bucket = d;
    } else {
        float l = logf((float)d / 16.0f) / logf(8.0f) * 16.0f;
        bucket = 16 + (int)l;
        if (bucket > 31) bucket = 31;
    }
    tab[h * SEQ + d] = emb[bucket * NHEADS + h];
}

// RMSNorm: one block per row of 1024
__global__ __launch_bounds__(256) void rmsnorm_k(
    const float* __restrict__ x, const float* __restrict__ g, float* __restrict__ o)
{
    __shared__ float sh[32];
    const int row = blockIdx.x;
    const float* xr = x + (size_t)row * DMODEL;
    const int t = threadIdx.x;
    float s = 0.f;
    for (int c = t; c < DMODEL; c += 256) { float v = xr[c]; s += v * v; }
#pragma unroll
    for (int off = 16; off > 0; off >>= 1) s += __shfl_xor_sync(0xffffffffu, s, off);
    if ((t & 31) == 0) sh[t >> 5] = s;
    __syncthreads();
    if (t < 32) {
        float v = (t < 8) ? sh[t] : 0.f;
#pragma unroll
        for (int off = 4; off > 0; off >>= 1) v += __shfl_xor_sync(0xffffffffu, v, off);
        if (t == 0) sh[0] = v;
    }
    __syncthreads();
    const float r = rsqrtf(sh[0] / (float)DMODEL + 1e-6f);
    float* orow = o + (size_t)row * DMODEL;
    for (int c = t; c < DMODEL; c += 256) orow[c] = g[c] * xr[c] * r;
}

// ---------------- generic SGEMM: C = A[MxK] @ B[KxN] (+ R) ----------------
// 128x128 block tile, BK=8, 8x8 per thread, 256 threads. M,N,K multiples of 128/8.
__global__ __launch_bounds__(256) void sgemm_k(
    const float* __restrict__ A, const float* __restrict__ B,
    const float* __restrict__ R, float* __restrict__ C,
    int M, int N, int K)
{
    __shared__ __align__(16) float As[8][128];
    __shared__ __align__(16) float Bs[8][128];
    const int t  = threadIdx.x;
    const int m0 = blockIdx.y * 128;
    const int n0 = blockIdx.x * 128;
    const int aRow = t >> 1;
    const int aCol = (t & 1) * 4;
    const int bRow = t >> 5;
    const int bCol = (t & 31) * 4;
    const int ty = t >> 4;
    const int tx = t & 15;
    const float* Ap = A + (size_t)(m0 + aRow) * K + aCol;
    const float* Bp = B + (size_t)bRow * N + n0 + bCol;
    float acc[8][8];
#pragma unroll
    for (int i = 0; i < 8; i++)
#pragma unroll
        for (int j = 0; j < 8; j++) acc[i][j] = 0.f;

    for (int k0 = 0; k0 < K; k0 += 8) {
        float4 av = *(const float4*)Ap;
        float4 bv = *(const float4*)(Bp + (size_t)k0 * N);
        As[aCol + 0][aRow] = av.x;
        As[aCol + 1][aRow] = av.y;
        As[aCol + 2][aRow] = av.z;
        As[aCol + 3][aRow] = av.w;
        *(float4*)&Bs[bRow][bCol] = bv;
        Ap += 8;
        __syncthreads();
#pragma unroll
        for (int kk = 0; kk < 8; kk++) {
            float4 a0 = *(const float4*)&As[kk][ty * 8];
            float4 a1 = *(const float4*)&As[kk][ty * 8 + 4];
            float4 b0 = *(const float4*)&Bs[kk][tx * 8];
            float4 b1 = *(const float4*)&Bs[kk][tx * 8 + 4];
            float ar[8] = {a0.x,a0.y,a0.z,a0.w,a1.x,a1.y,a1.z,a1.w};
            float br[8] = {b0.x,b0.y,b0.z,b0.w,b1.x,b1.y,b1.z,b1.w};
#pragma unroll
            for (int i = 0; i < 8; i++)
#pragma unroll
                for (int j = 0; j < 8; j++)
                    acc[i][j] += ar[i] * br[j];
        }
        __syncthreads();
    }
#pragma unroll
    for (int i = 0; i < 8; i++) {
        size_t off = (size_t)(m0 + ty * 8 + i) * N + n0 + tx * 8;
        if (R) {
#pragma unroll
            for (int j = 0; j < 8; j++) C[off + j] = acc[i][j] + R[off + j];
        } else {
#pragma unroll
            for (int j = 0; j < 8; j++) C[off + j] = acc[i][j];
        }
    }
}

// ---------------- attention scores: S = Q K^T + bias + mask ----------------
// grid (SEQ/64, SEQ/64, BATCH*NHEADS); 64x64 tile, K=64; smem stored [d][row]
__global__ __launch_bounds__(256) void scores_k(
    const float* __restrict__ Q, const float* __restrict__ Kv,
    float* __restrict__ S, const float* __restrict__ biasTab,
    const float* __restrict__ mask, int selfMode)
{
    __shared__ __align__(16) float Qs[64][68];
    __shared__ __align__(16) float Ks[64][68];
    const int bh = blockIdx.z;
    const int b  = bh >> 4;
    const int h  = bh & 15;
    const int i0 = blockIdx.y * 64;
    const int j0 = blockIdx.x * 64;
    const int t  = threadIdx.x;
    const int lr = t >> 2;
    const int lc = (t & 3) * 16;
    const float* qp = Q  + (size_t)(b * SEQ + i0 + lr) * DMODEL + h * HDIM + lc;
    const float* kp = Kv + (size_t)(b * SEQ + j0 + lr) * DMODEL + h * HDIM + lc;
#pragma unroll
    for (int u = 0; u < 4; u++) {
        float4 qv = *(const float4*)(qp + u * 4);
        Qs[lc + u*4 + 0][lr] = qv.x;
        Qs[lc + u*4 + 1][lr] = qv.y;
        Qs[lc + u*4 + 2][lr] = qv.z;
        Qs[lc + u*4 + 3][lr] = qv.w;
        float4 kv = *(const float4*)(kp + u * 4);
        Ks[lc + u*4 + 0][lr] = kv.x;
        Ks[lc + u*4 + 1][lr] = kv.y;
        Ks[lc + u*4 + 2][lr] = kv.z;
        Ks[lc + u*4 + 3][lr] = kv.w;
    }
    __syncthreads();
    const int ty = t >> 4, tx = t & 15;
    float acc[4][4] = {};
#pragma unroll 16
    for (int d = 0; d < 64; d++) {
        float4 qv = *(const float4*)&Qs[d][ty * 4];
        float4 kv = *(const float4*)&Ks[d][tx * 4];
        float qa[4] = {qv.x, qv.y, qv.z, qv.w};
        float ka[4] = {kv.x, kv.y, kv.z, kv.w};
#pragma unroll
        for (int r = 0; r < 4; r++)
#pragma unroll
            for (int c = 0; c < 4; c++)
                acc[r][c] += qa[r] * ka[c];
    }
#pragma unroll
    for (int r = 0; r < 4; r++) {
        const int gi = i0 + ty * 4 + r;
        const size_t srow = ((size_t)bh * SEQ + gi) * SEQ;
#pragma unroll
        for (int c = 0; c < 4; c++) {
            const int gj = j0 + tx * 4 + c;
            float v = acc[r][c];
            if (selfMode) {
                int dd = gi - gj; if (dd < 0) dd = 0;
                v += biasTab[h * SEQ + dd]
                   + mask[(size_t)b * SEQ * SEQ + (size_t)gi * SEQ + gj];
            } else {
                v += mask[(size_t)b * SEQ + gj];
            }
            S[srow + gj] = v;
        }
    }
}

// ---------------- row softmax over 1024 cols ----------------
__global__ __launch_bounds__(256) void softmax_k(float* __restrict__ S)
{
    __shared__ float sh[32];
    const size_t row = blockIdx.x;
    float* p = S + row * SEQ;
    const int t = threadIdx.x;
    float v[4];
    float mx = -3.4e38f;
#pragma unroll
    for (int u = 0; u < 4; u++) { v[u] = p[t + u * 256]; mx = fmaxf(mx, v[u]); }
#pragma unroll
    for (int off = 16; off > 0; off >>= 1) mx = fmaxf(mx, __shfl_xor_sync(0xffffffffu, mx, off));
    if ((t & 31) == 0) sh[t >> 5] = mx;
    __syncthreads();
    if (t < 32) {
        float m2 = (t < 8) ? sh[t] : -3.4e38f;
#pragma unroll
        for (int off = 4; off > 0; off >>= 1) m2 = fmaxf(m2, __shfl_xor_sync(0xffffffffu, m2, off));
        if (t == 0) sh[0] = m2;
    }
    __syncthreads();
    const float mxa = sh[0];
    __syncthreads();
    float s = 0.f;
#pragma unroll
    for (int u = 0; u < 4; u++) { v[u] = expf(v[u] - mxa); s += v[u]; }
#pragma unroll
    for (int off = 16; off > 0; off >>= 1) s += __shfl_xor_sync(0xffffffffu, s, off);
    if ((t & 31) == 0) sh[t >> 5] = s;
    __syncthreads();
    if (t < 32) {
        float s2 = (t < 8) ? sh[t] : 0.f;
#pragma unroll
        for (int off = 4; off > 0; off >>= 1) s2 += __shfl_xor_sync(0xffffffffu, s2, off);
        if (t == 0) sh[0] = s2;
    }
    __syncthreads();
    const float inv = 1.0f / sh[0];
#pragma unroll
    for (int u = 0; u < 4; u++) p[t + u * 256] = v[u] * inv;
}

// ---------------- O = P @ V (per b,h): M=1024, N=64, K=1024 ----------------
__global__ __launch_bounds__(256) void av_k(
    const float* __restrict__ S, const float* __restrict__ V, float* __restrict__ O)
{
    __shared__ __align__(16) float Ps[64][68];   // [k][row]
    __shared__ __align__(16) float Vs[64][68];   // [k][dim]
    const int bh = blockIdx.y;
    const int b  = bh >> 4, h = bh & 15;
    const int i0 = blockIdx.x * 64;
    const int t  = threadIdx.x;
    const int lr = t >> 2, lc = (t & 3) * 16;
    const int ty = t >> 4, tx = t & 15;
    float acc[4][4] = {};
    const float* sp = S + ((size_t)bh * SEQ + i0 + lr) * SEQ + lc;
    const float* vp = V + (size_t)(b * SEQ + lr) * DMODEL + h * HDIM + lc;
    for (int j0 = 0; j0 < SEQ; j0 += 64) {
#pragma unroll
        for (int u = 0; u < 4; u++) {
            float4 pv = *(const float4*)(sp + j0 + u * 4);
            Ps[lc + u*4 + 0][lr] = pv.x;
            Ps[lc + u*4 + 1][lr] = pv.y;
            Ps[lc + u*4 + 2][lr] = pv.z;
            Ps[lc + u*4 + 3][lr] = pv.w;
            float4 vv = *(const float4*)(vp + (size_t)j0 * DMODEL + u * 4);
            *(float4*)&Vs[lr][lc + u * 4] = vv;
        }
        __syncthreads();
#pragma unroll 16
        for (int k = 0; k < 64; k++) {
            float4 pv4 = *(const float4*)&Ps[k][ty * 4];
            float4 vv4 = *(const float4*)&Vs[k][tx * 4];
            float pa[4] = {pv4.x, pv4.y, pv4.z, pv4.w};
            float va[4] = {vv4.x, vv4.y, vv4.z, vv4.w};
#pragma unroll
            for (int r = 0; r < 4; r++)
#pragma unroll
                for (int c = 0; c < 4; c++)
                    acc[r][c] += pa[r] * va[c];
        }
        __syncthreads();
    }
#pragma unroll
    for (int r = 0; r < 4; r++) {
        size_t off = (size_t)(b * SEQ + i0 + ty * 4 + r) * DMODEL + h * HDIM + tx * 4;
#pragma unroll
        for (int c = 0; c < 4; c++) O[off + c] = acc[r][c];
    }
}

// ---------------- GeGLU combine: t0 = gelu_exact(t0) * t1 ----------------
__global__ void geglu_k(float* __restrict__ t0, const float* __restrict__ t1, int n) {
    int i = blockIdx.x * blockDim.x + threadIdx.x;
    if (i < n) {
        float x = t0[i];
        float g = 0.5f * x * (1.0f + erff(x * 0.70710678118654752f));
        t0[i] = g * t1[i];
    }
}

// ---------------- host orchestration ----------------
extern "C" void kernel_launch(void* const* d_in, const int* in_sizes, int n_in,
                              void* d_out, int out_size)
{
    const float* hs    = (const float*)d_in[0];
    const float* enc   = (const float*)d_in[1];
    const float* amask = (const float*)d_in[2];
    const float* emask = (const float*)d_in[3];
    const float* Wq_s  = (const float*)d_in[4];
    const float* Wk_s  = (const float*)d_in[5];
    const float* Wv_s  = (const float*)d_in[6];
    const float* Wo_s  = (const float*)d_in[7];
    const float* Wq_c  = (const float*)d_in[8];
    const float* Wk_c  = (const float*)d_in[9];
    const float* Wv_c  = (const float*)d_in[10];
    const float* Wo_c  = (const float*)d_in[11];
    const float* Wi0   = (const float*)d_in[12];
    const float* Wi1   = (const float*)d_in[13];
    const float* Wof   = (const float*)d_in[14];
    const float* g1    = (const float*)d_in[15];
    const float* g2    = (const float*)d_in[16];
    const float* g3    = (const float*)d_in[17];
    const float* gf    = (const float*)d_in[18];
    const float* remb  = (const float*)d_in[19];

    static float *px = nullptr, *pn, *pq, *pk, *pv, *pa, *ps, *pt0, *pt1, *pb;
    if (!px) {
        cudaGetSymbolAddress((void**)&px,  g_x);
        cudaGetSymbolAddress((void**)&pn,  g_nb);
        cudaGetSymbolAddress((void**)&pq,  g_qb);
        cudaGetSymbolAddress((void**)&pk,  g_kb);
        cudaGetSymbolAddress((void**)&pv,  g_vb);
        cudaGetSymbolAddress((void**)&pa,  g_ab);
        cudaGetSymbolAddress((void**)&ps,  g_sb);
        cudaGetSymbolAddress((void**)&pt0, g_t0b);
        cudaGetSymbolAddress((void**)&pt1, g_t1b);
        cudaGetSymbolAddress((void**)&pb,  g_biasb);
    }

    const dim3 gD(DMODEL / 128, MROWS / 128);   // (8, 16)
    const dim3 gF(FFDIM / 128,  MROWS / 128);   // (32, 16)
    const dim3 gS(SEQ / 64, SEQ / 64, BATCH * NHEADS);
    const dim3 gA(SEQ / 64, BATCH * NHEADS);
    const int softmaxBlocks = BATCH * NHEADS * SEQ;

    copy4_k<<<(MROWS * DMODEL / 4 + 255) / 256, 256>>>(hs, px, MROWS * DMODEL / 4);
    biastab_k<<<(NHEADS * SEQ + 255) / 256, 256>>>(remb, pb);

    for (int i = 0; i < NLAYERS; i++) {
        const size_t oD = (size_t)i * DMODEL * DMODEL;
        // --- causal self-attention with rel-pos bias ---
        rmsnorm_k<<<MROWS, 256>>>(px, g1 + i * DMODEL, pn);
        sgemm_k<<<gD, 256>>>(pn, Wq_s + oD, nullptr, pq, MROWS, DMODEL, DMODEL);
        sgemm_k<<<gD, 256>>>(pn, Wk_s + oD, nullptr, pk, MROWS, DMODEL, DMODEL);
        sgemm_k<<<gD, 256>>>(pn, Wv_s + oD, nullptr, pv, MROWS, DMODEL, DMODEL);
        scores_k<<<gS, 256>>>(pq, pk, ps, pb, amask, 1);
        softmax_k<<<softmaxBlocks, 256>>>(ps);
        av_k<<<gA, 256>>>(ps, pv, pa);
        sgemm_k<<<gD, 256>>>(pa, Wo_s + oD, px, px, MROWS, DMODEL, DMODEL);
        // --- cross-attention (K/V from raw encoder states) ---
        rmsnorm_k<<<MROWS, 256>>>(px, g2 + i * DMODEL, pn);
        sgemm_k<<<gD, 256>>>(pn,  Wq_c + oD, nullptr, pq, MROWS, DMODEL, DMODEL);
        sgemm_k<<<gD, 256>>>(enc, Wk_c + oD, nullptr, pk, MROWS, DMODEL, DMODEL);
        sgemm_k<<<gD, 256>>>(enc, Wv_c + oD, nullptr, pv, MROWS, DMODEL, DMODEL);
        scores_k<<<gS, 256>>>(pq, pk, ps, pb, emask, 0);
        softmax_k<<<softmaxBlocks, 256>>>(ps);
        av_k<<<gA, 256>>>(ps, pv, pa);
        sgemm_k<<<gD, 256>>>(pa, Wo_c + oD, px, px, MROWS, DMODEL, DMODEL);
        // --- GeGLU FFN ---
        const size_t oF = (size_t)i * DMODEL * FFDIM;
        rmsnorm_k<<<MROWS, 256>>>(px, g3 + i * DMODEL, pn);
        sgemm_k<<<gF, 256>>>(pn, Wi0 + oF, nullptr, pt0, MROWS, FFDIM, DMODEL);
        sgemm_k<<<gF, 256>>>(pn, Wi1 + oF, nullptr, pt1, MROWS, FFDIM, DMODEL);
        geglu_k<<<(MROWS * FFDIM + 255) / 256, 256>>>(pt0, pt1, MROWS * FFDIM);
        sgemm_k<<<gD, 256>>>(pt0, Wof + (size_t)i * FFDIM * DMODEL, px, px,
                             MROWS, DMODEL, FFDIM);
    }
    rmsnorm_k<<<MROWS, 256>>>(px, gf, (float*)d_out);
}

// round 7
// speedup vs baseline: 1.9180x; 1.9180x over previous
#include <cuda_runtime.h>
#include <math.h>

#define NLAYERS 4
#define DMODEL 1024
#define NHEADS 16
#define HDIM 64
#define FFDIM 4096
#define BATCH 2
#define SEQ 1024
#define MROWS (BATCH*SEQ)   // 2048

// ---------------- scratch (no allocations allowed) ----------------
__device__ float g_x [(size_t)MROWS*DMODEL];
__device__ float g_nb[(size_t)MROWS*DMODEL];
__device__ float g_qb[(size_t)MROWS*DMODEL];
__device__ float g_kb[(size_t)MROWS*DMODEL];
__device__ float g_vb[(size_t)MROWS*DMODEL];
__device__ float g_ab[(size_t)MROWS*DMODEL];
__device__ float g_sb[(size_t)BATCH*NHEADS*SEQ*SEQ];   // 128 MB scores
__device__ float g_t0b[(size_t)MROWS*FFDIM];
__device__ float g_t1b[(size_t)MROWS*FFDIM];
__device__ float g_biasb[NHEADS*SEQ];

// ---------------- small utility kernels ----------------
__global__ void copy4_k(const float* __restrict__ src, float* __restrict__ dst, int n4) {
    int i = blockIdx.x * blockDim.x + threadIdx.x;
    if (i < n4) ((float4*)dst)[i] = ((const float4*)src)[i];
}

// bias table: tab[h*SEQ + delta] = rel_emb[bucket(delta)][h], delta = max(i-j,0)
__global__ void biastab_k(const float* __restrict__ emb, float* __restrict__ tab) {
    int idx = blockIdx.x * blockDim.x + threadIdx.x;
    if (idx >= NHEADS * SEQ) return;
    int h = idx / SEQ;
    int d = idx % SEQ;
    int bucket;
    if (d < 16) {
        bucket = d;
    } else {
        float l = logf((float)d / 16.0f) / logf(8.0f) * 16.0f;
        bucket = 16 + (int)l;
        if (bucket > 31) bucket = 31;
    }
    tab[h * SEQ + d] = emb[bucket * NHEADS + h];
}

// RMSNorm: one block per row of 1024
__global__ __launch_bounds__(256) void rmsnorm_k(
    const float* __restrict__ x, const float* __restrict__ g, float* __restrict__ o)
{
    __shared__ float sh[32];
    const int row = blockIdx.x;
    const float* xr = x + (size_t)row * DMODEL;
    const int t = threadIdx.x;
    float s = 0.f;
    for (int c = t; c < DMODEL; c += 256) { float v = xr[c]; s += v * v; }
#pragma unroll
    for (int off = 16; off > 0; off >>= 1) s += __shfl_xor_sync(0xffffffffu, s, off);
    if ((t & 31) == 0) sh[t >> 5] = s;
    __syncthreads();
    if (t < 32) {
        float v = (t < 8) ? sh[t] : 0.f;
#pragma unroll
        for (int off = 4; off > 0; off >>= 1) v += __shfl_xor_sync(0xffffffffu, v, off);
        if (t == 0) sh[0] = v;
    }
    __syncthreads();
    const float r = rsqrtf(sh[0] / (float)DMODEL + 1e-6f);
    float* orow = o + (size_t)row * DMODEL;
    for (int c = t; c < DMODEL; c += 256) orow[c] = g[c] * xr[c] * r;
}

// ---------------- TF32 helpers ----------------
__device__ __forceinline__ float f2tf(float f) {
    unsigned u;
    asm("cvt.rna.tf32.f32 %0, %1;" : "=r"(u) : "f"(f));
    return __uint_as_float(u);
}

__device__ __forceinline__ void mma_tf32(
    float* d, const unsigned* a, const unsigned* b)
{
    asm volatile(
        "mma.sync.aligned.m16n8k8.row.col.f32.tf32.tf32.f32 "
        "{%0,%1,%2,%3}, {%4,%5,%6,%7}, {%8,%9}, {%0,%1,%2,%3};"
        : "+f"(d[0]), "+f"(d[1]), "+f"(d[2]), "+f"(d[3])
        : "r"(a[0]), "r"(a[1]), "r"(a[2]), "r"(a[3]),
          "r"(b[0]), "r"(b[1]));
}

// ---------------- TF32 tensor-core GEMM: C = A[MxK] @ B[KxN] (+ R) ----------
// 128x128 CTA tile, BK=16, 8 warps (2x4), warp tile 64x32 = 4x4 m16n8k8 frags.
// Double-buffered smem; inputs rounded to tf32 at the global->smem stage.
// Smem stride 140 floats => conflict-free tiled stores AND fragment loads.
__global__ __launch_bounds__(256) void mm_tf32_k(
    const float* __restrict__ A, const float* __restrict__ B,
    const float* __restrict__ R, float* __restrict__ C,
    int M, int N, int K)
{
    __shared__ __align__(16) float As[2][16][140];
    __shared__ __align__(16) float Bs[2][16][140];
    const int t  = threadIdx.x;
    const int m0 = blockIdx.y * 128;
    const int n0 = blockIdx.x * 128;

    // A tile 128x16: two float4 loads per thread; row = (i>>1)&127, kc per i
    const int aRow = (t >> 1) & 127;
    const int aKc0 = (t & 1) * 4;       // i = t       -> kc 0 / 4
    const int aKc1 = aKc0 + 8;          // i = t + 256 -> kc 8 / 12
    // B tile 16x128: row = i>>5, col = (i&31)*4
    const int bRow = t >> 5;            // 0..7 (i=t), +8 for i=t+256
    const int bCol = (t & 31) * 4;

    const int lane = t & 31, warp = t >> 5;
    const int wm  = (warp >> 2) * 64;   // warp M offset (2 warps in M)
    const int wn  = (warp & 3)  * 32;   // warp N offset (4 warps in N)
    const int gid = lane >> 2, tig = lane & 3;

    float acc[4][4][4];
#pragma unroll
    for (int i = 0; i < 4; i++)
#pragma unroll
        for (int j = 0; j < 4; j++)
#pragma unroll
            for (int r = 0; r < 4; r++) acc[i][j][r] = 0.f;

    const float* Ap0 = A + (size_t)(m0 + aRow) * K;
    const float* Bp0 = B + n0 + bCol;

    // prologue: load tile k0=0 into buffer 0
    float4 av0 = *(const float4*)(Ap0 + aKc0);
    float4 av1 = *(const float4*)(Ap0 + aKc1);
    float4 bv0 = *(const float4*)(Bp0 + (size_t)bRow * N);
    float4 bv1 = *(const float4*)(Bp0 + (size_t)(bRow + 8) * N);
    {
        As[0][aKc0+0][aRow]=f2tf(av0.x); As[0][aKc0+1][aRow]=f2tf(av0.y);
        As[0][aKc0+2][aRow]=f2tf(av0.z); As[0][aKc0+3][aRow]=f2tf(av0.w);
        As[0][aKc1+0][aRow]=f2tf(av1.x); As[0][aKc1+1][aRow]=f2tf(av1.y);
        As[0][aKc1+2][aRow]=f2tf(av1.z); As[0][aKc1+3][aRow]=f2tf(av1.w);
        float4 c0 = make_float4(f2tf(bv0.x),f2tf(bv0.y),f2tf(bv0.z),f2tf(bv0.w));
        float4 c1 = make_float4(f2tf(bv1.x),f2tf(bv1.y),f2tf(bv1.z),f2tf(bv1.w));
        *(float4*)&Bs[0][bRow  ][bCol] = c0;
        *(float4*)&Bs[0][bRow+8][bCol] = c1;
    }
    __syncthreads();

    int cur = 0;
    for (int k0 = 0; k0 < K; k0 += 16) {
        const bool last = (k0 + 16 >= K);
        if (!last) {
            const float* Ap = Ap0 + k0 + 16;
            av0 = *(const float4*)(Ap + aKc0);
            av1 = *(const float4*)(Ap + aKc1);
            bv0 = *(const float4*)(Bp0 + (size_t)(k0 + 16 + bRow) * N);
            bv1 = *(const float4*)(Bp0 + (size_t)(k0 + 16 + bRow + 8) * N);
        }
#pragma unroll
        for (int ks = 0; ks < 2; ks++) {
            const int kk = ks * 8;
            unsigned a[4][4], b[4][2];
#pragma unroll
            for (int mt = 0; mt < 4; mt++) {
                const int r = wm + mt * 16 + gid;
                a[mt][0] = __float_as_uint(As[cur][kk+tig  ][r]);
                a[mt][1] = __float_as_uint(As[cur][kk+tig  ][r+8]);
                a[mt][2] = __float_as_uint(As[cur][kk+tig+4][r]);
                a[mt][3] = __float_as_uint(As[cur][kk+tig+4][r+8]);
            }
#pragma unroll
            for (int nt = 0; nt < 4; nt++) {
                const int c = wn + nt * 8 + gid;
                b[nt][0] = __float_as_uint(Bs[cur][kk+tig  ][c]);
                b[nt][1] = __float_as_uint(Bs[cur][kk+tig+4][c]);
            }
#pragma unroll
            for (int mt = 0; mt < 4; mt++)
#pragma unroll
                for (int nt = 0; nt < 4; nt++)
                    mma_tf32(acc[mt][nt], a[mt], b[nt]);
        }
        if (!last) {
            const int nxt = cur ^ 1;
            As[nxt][aKc0+0][aRow]=f2tf(av0.x); As[nxt][aKc0+1][aRow]=f2tf(av0.y);
            As[nxt][aKc0+2][aRow]=f2tf(av0.z); As[nxt][aKc0+3][aRow]=f2tf(av0.w);
            As[nxt][aKc1+0][aRow]=f2tf(av1.x); As[nxt][aKc1+1][aRow]=f2tf(av1.y);
            As[nxt][aKc1+2][aRow]=f2tf(av1.z); As[nxt][aKc1+3][aRow]=f2tf(av1.w);
            float4 c0 = make_float4(f2tf(bv0.x),f2tf(bv0.y),f2tf(bv0.z),f2tf(bv0.w));
            float4 c1 = make_float4(f2tf(bv1.x),f2tf(bv1.y),f2tf(bv1.z),f2tf(bv1.w));
            *(float4*)&Bs[nxt][bRow  ][bCol] = c0;
            *(float4*)&Bs[nxt][bRow+8][bCol] = c1;
            __syncthreads();
            cur = nxt;
        }
    }

    // epilogue: c0,c1 -> row r, cols 2*tig,2*tig+1 ; c2,c3 -> row r+8
#pragma unroll
    for (int mt = 0; mt < 4; mt++) {
        const int r = m0 + wm + mt * 16 + gid;
#pragma unroll
        for (int nt = 0; nt < 4; nt++) {
            const int c = n0 + wn + nt * 8 + 2 * tig;
            const size_t o0 = (size_t)r * N + c;
            const size_t o1 = (size_t)(r + 8) * N + c;
            if (R) {
                C[o0]   = acc[mt][nt][0] + R[o0];
                C[o0+1] = acc[mt][nt][1] + R[o0+1];
                C[o1]   = acc[mt][nt][2] + R[o1];
                C[o1+1] = acc[mt][nt][3] + R[o1+1];
            } else {
                C[o0]   = acc[mt][nt][0];
                C[o0+1] = acc[mt][nt][1];
                C[o1]   = acc[mt][nt][2];
                C[o1+1] = acc[mt][nt][3];
            }
        }
    }
}

// ---------------- attention scores: S = Q K^T + bias + mask ----------------
__global__ __launch_bounds__(256) void scores_k(
    const float* __restrict__ Q, const float* __restrict__ Kv,
    float* __restrict__ S, const float* __restrict__ biasTab,
    const float* __restrict__ mask, int selfMode)
{
    __shared__ __align__(16) float Qs[64][68];
    __shared__ __align__(16) float Ks[64][68];
    const int bh = blockIdx.z;
    const int b  = bh >> 4;
    const int h  = bh & 15;
    const int i0 = blockIdx.y * 64;
    const int j0 = blockIdx.x * 64;
    const int t  = threadIdx.x;
    const int lr = t >> 2;
    const int lc = (t & 3) * 16;
    const float* qp = Q  + (size_t)(b * SEQ + i0 + lr) * DMODEL + h * HDIM + lc;
    const float* kp = Kv + (size_t)(b * SEQ + j0 + lr) * DMODEL + h * HDIM + lc;
#pragma unroll
    for (int u = 0; u < 4; u++) {
        float4 qv = *(const float4*)(qp + u * 4);
        Qs[lc + u*4 + 0][lr] = qv.x;
        Qs[lc + u*4 + 1][lr] = qv.y;
        Qs[lc + u*4 + 2][lr] = qv.z;
        Qs[lc + u*4 + 3][lr] = qv.w;
        float4 kv = *(const float4*)(kp + u * 4);
        Ks[lc + u*4 + 0][lr] = kv.x;
        Ks[lc + u*4 + 1][lr] = kv.y;
        Ks[lc + u*4 + 2][lr] = kv.z;
        Ks[lc + u*4 + 3][lr] = kv.w;
    }
    __syncthreads();
    const int ty = t >> 4, tx = t & 15;
    float acc[4][4] = {};
#pragma unroll 16
    for (int d = 0; d < 64; d++) {
        float4 qv = *(const float4*)&Qs[d][ty * 4];
        float4 kv = *(const float4*)&Ks[d][tx * 4];
        float qa[4] = {qv.x, qv.y, qv.z, qv.w};
        float ka[4] = {kv.x, kv.y, kv.z, kv.w};
#pragma unroll
        for (int r = 0; r < 4; r++)
#pragma unroll
            for (int c = 0; c < 4; c++)
                acc[r][c] += qa[r] * ka[c];
    }
#pragma unroll
    for (int r = 0; r < 4; r++) {
        const int gi = i0 + ty * 4 + r;
        const size_t srow = ((size_t)bh * SEQ + gi) * SEQ;
#pragma unroll
        for (int c = 0; c < 4; c++) {
            const int gj = j0 + tx * 4 + c;
            float v = acc[r][c];
            if (selfMode) {
                int dd = gi - gj; if (dd < 0) dd = 0;
                v += biasTab[h * SEQ + dd]
                   + mask[(size_t)b * SEQ * SEQ + (size_t)gi * SEQ + gj];
            } else {
                v += mask[(size_t)b * SEQ + gj];
            }
            S[srow + gj] = v;
        }
    }
}

// ---------------- row softmax over 1024 cols ----------------
__global__ __launch_bounds__(256) void softmax_k(float* __restrict__ S)
{
    __shared__ float sh[32];
    const size_t row = blockIdx.x;
    float* p = S + row * SEQ;
    const int t = threadIdx.x;
    float v[4];
    float mx = -3.4e38f;
#pragma unroll
    for (int u = 0; u < 4; u++) { v[u] = p[t + u * 256]; mx = fmaxf(mx, v[u]); }
#pragma unroll
    for (int off = 16; off > 0; off >>= 1) mx = fmaxf(mx, __shfl_xor_sync(0xffffffffu, mx, off));
    if ((t & 31) == 0) sh[t >> 5] = mx;
    __syncthreads();
    if (t < 32) {
        float m2 = (t < 8) ? sh[t] : -3.4e38f;
#pragma unroll
        for (int off = 4; off > 0; off >>= 1) m2 = fmaxf(m2, __shfl_xor_sync(0xffffffffu, m2, off));
        if (t == 0) sh[0] = m2;
    }
    __syncthreads();
    const float mxa = sh[0];
    __syncthreads();
    float s = 0.f;
#pragma unroll
    for (int u = 0; u < 4; u++) { v[u] = expf(v[u] - mxa); s += v[u]; }
#pragma unroll
    for (int off = 16; off > 0; off >>= 1) s += __shfl_xor_sync(0xffffffffu, s, off);
    if ((t & 31) == 0) sh[t >> 5] = s;
    __syncthreads();
    if (t < 32) {
        float s2 = (t < 8) ? sh[t] : 0.f;
#pragma unroll
        for (int off = 4; off > 0; off >>= 1) s2 += __shfl_xor_sync(0xffffffffu, s2, off);
        if (t == 0) sh[0] = s2;
    }
    __syncthreads();
    const float inv = 1.0f / sh[0];
#pragma unroll
    for (int u = 0; u < 4; u++) p[t + u * 256] = v[u] * inv;
}

// ---------------- O = P @ V (per b,h): M=1024, N=64, K=1024 ----------------
__global__ __launch_bounds__(256) void av_k(
    const float* __restrict__ S, const float* __restrict__ V, float* __restrict__ O)
{
    __shared__ __align__(16) float Ps[64][68];   // [k][row]
    __shared__ __align__(16) float Vs[64][68];   // [k][dim]
    const int bh = blockIdx.y;
    const int b  = bh >> 4, h = bh & 15;
    const int i0 = blockIdx.x * 64;
    const int t  = threadIdx.x;
    const int lr = t >> 2, lc = (t & 3) * 16;
    const int ty = t >> 4, tx = t & 15;
    float acc[4][4] = {};
    const float* sp = S + ((size_t)bh * SEQ + i0 + lr) * SEQ + lc;
    const float* vp = V + (size_t)(b * SEQ + lr) * DMODEL + h * HDIM + lc;
    for (int j0 = 0; j0 < SEQ; j0 += 64) {
#pragma unroll
        for (int u = 0; u < 4; u++) {
            float4 pv = *(const float4*)(sp + j0 + u * 4);
            Ps[lc + u*4 + 0][lr] = pv.x;
            Ps[lc + u*4 + 1][lr] = pv.y;
            Ps[lc + u*4 + 2][lr] = pv.z;
            Ps[lc + u*4 + 3][lr] = pv.w;
            float4 vv = *(const float4*)(vp + (size_t)j0 * DMODEL + u * 4);
            *(float4*)&Vs[lr][lc + u * 4] = vv;
        }
        __syncthreads();
#pragma unroll 16
        for (int k = 0; k < 64; k++) {
            float4 pv4 = *(const float4*)&Ps[k][ty * 4];
            float4 vv4 = *(const float4*)&Vs[k][tx * 4];
            float pa[4] = {pv4.x, pv4.y, pv4.z, pv4.w};
            float va[4] = {vv4.x, vv4.y, vv4.z, vv4.w};
#pragma unroll
            for (int r = 0; r < 4; r++)
#pragma unroll
                for (int c = 0; c < 4; c++)
                    acc[r][c] += pa[r] * va[c];
        }
        __syncthreads();
    }
#pragma unroll
    for (int r = 0; r < 4; r++) {
        size_t off = (size_t)(b * SEQ + i0 + ty * 4 + r) * DMODEL + h * HDIM + tx * 4;
#pragma unroll
        for (int c = 0; c < 4; c++) O[off + c] = acc[r][c];
    }
}

// ---------------- GeGLU combine: t0 = gelu_exact(t0) * t1 ----------------
__global__ void geglu_k(float* __restrict__ t0, const float* __restrict__ t1, int n) {
    int i = blockIdx.x * blockDim.x + threadIdx.x;
    if (i < n) {
        float x = t0[i];
        float g = 0.5f * x * (1.0f + erff(x * 0.70710678118654752f));
        t0[i] = g * t1[i];
    }
}

// ---------------- host orchestration ----------------
extern "C" void kernel_launch(void* const* d_in, const int* in_sizes, int n_in,
                              void* d_out, int out_size)
{
    const float* hs    = (const float*)d_in[0];
    const float* enc   = (const float*)d_in[1];
    const float* amask = (const float*)d_in[2];
    const float* emask = (const float*)d_in[3];
    const float* Wq_s  = (const float*)d_in[4];
    const float* Wk_s  = (const float*)d_in[5];
    const float* Wv_s  = (const float*)d_in[6];
    const float* Wo_s  = (const float*)d_in[7];
    const float* Wq_c  = (const float*)d_in[8];
    const float* Wk_c  = (const float*)d_in[9];
    const float* Wv_c  = (const float*)d_in[10];
    const float* Wo_c  = (const float*)d_in[11];
    const float* Wi0   = (const float*)d_in[12];
    const float* Wi1   = (const float*)d_in[13];
    const float* Wof   = (const float*)d_in[14];
    const float* g1    = (const float*)d_in[15];
    const float* g2    = (const float*)d_in[16];
    const float* g3    = (const float*)d_in[17];
    const float* gf    = (const float*)d_in[18];
    const float* remb  = (const float*)d_in[19];

    static float *px = nullptr, *pn, *pq, *pk, *pv, *pa, *ps, *pt0, *pt1, *pb;
    if (!px) {
        cudaGetSymbolAddress((void**)&px,  g_x);
        cudaGetSymbolAddress((void**)&pn,  g_nb);
        cudaGetSymbolAddress((void**)&pq,  g_qb);
        cudaGetSymbolAddress((void**)&pk,  g_kb);
        cudaGetSymbolAddress((void**)&pv,  g_vb);
        cudaGetSymbolAddress((void**)&pa,  g_ab);
        cudaGetSymbolAddress((void**)&ps,  g_sb);
        cudaGetSymbolAddress((void**)&pt0, g_t0b);
        cudaGetSymbolAddress((void**)&pt1, g_t1b);
        cudaGetSymbolAddress((void**)&pb,  g_biasb);
    }

    const dim3 gD(DMODEL / 128, MROWS / 128);   // (8, 16)
    const dim3 gF(FFDIM / 128,  MROWS / 128);   // (32, 16)
    const dim3 gS(SEQ / 64, SEQ / 64, BATCH * NHEADS);
    const dim3 gA(SEQ / 64, BATCH * NHEADS);
    const int softmaxBlocks = BATCH * NHEADS * SEQ;

    copy4_k<<<(MROWS * DMODEL / 4 + 255) / 256, 256>>>(hs, px, MROWS * DMODEL / 4);
    biastab_k<<<(NHEADS * SEQ + 255) / 256, 256>>>(remb, pb);

    for (int i = 0; i < NLAYERS; i++) {
        const size_t oD = (size_t)i * DMODEL * DMODEL;
        // --- causal self-attention with rel-pos bias ---
        rmsnorm_k<<<MROWS, 256>>>(px, g1 + i * DMODEL, pn);
        mm_tf32_k<<<gD, 256>>>(pn, Wq_s + oD, nullptr, pq, MROWS, DMODEL, DMODEL);
        mm_tf32_k<<<gD, 256>>>(pn, Wk_s + oD, nullptr, pk, MROWS, DMODEL, DMODEL);
        mm_tf32_k<<<gD, 256>>>(pn, Wv_s + oD, nullptr, pv, MROWS, DMODEL, DMODEL);
        scores_k<<<gS, 256>>>(pq, pk, ps, pb, amask, 1);
        softmax_k<<<softmaxBlocks, 256>>>(ps);
        av_k<<<gA, 256>>>(ps, pv, pa);
        mm_tf32_k<<<gD, 256>>>(pa, Wo_s + oD, px, px, MROWS, DMODEL, DMODEL);
        // --- cross-attention (K/V from raw encoder states) ---
        rmsnorm_k<<<MROWS, 256>>>(px, g2 + i * DMODEL, pn);
        mm_tf32_k<<<gD, 256>>>(pn,  Wq_c + oD, nullptr, pq, MROWS, DMODEL, DMODEL);
        mm_tf32_k<<<gD, 256>>>(enc, Wk_c + oD, nullptr, pk, MROWS, DMODEL, DMODEL);
        mm_tf32_k<<<gD, 256>>>(enc, Wv_c + oD, nullptr, pv, MROWS, DMODEL, DMODEL);
        scores_k<<<gS, 256>>>(pq, pk, ps, pb, emask, 0);
        softmax_k<<<softmaxBlocks, 256>>>(ps);
        av_k<<<gA, 256>>>(ps, pv, pa);
        mm_tf32_k<<<gD, 256>>>(pa, Wo_c + oD, px, px, MROWS, DMODEL, DMODEL);
        // --- GeGLU FFN ---
        const size_t oF = (size_t)i * DMODEL * FFDIM;
        rmsnorm_k<<<MROWS, 256>>>(px, g3 + i * DMODEL, pn);
        mm_tf32_k<<<gF, 256>>>(pn, Wi0 + oF, nullptr, pt0, MROWS, FFDIM, DMODEL);
        mm_tf32_k<<<gF, 256>>>(pn, Wi1 + oF, nullptr, pt1, MROWS, FFDIM, DMODEL);
        geglu_k<<<(MROWS * FFDIM + 255) / 256, 256>>>(pt0, pt1, MROWS * FFDIM);
        mm_tf32_k<<<gD, 256>>>(pt0, Wof + (size_t)i * FFDIM * DMODEL, px, px,
                               MROWS, DMODEL, FFDIM);
    }
    rmsnorm_k<<<MROWS, 256>>>(px, gf, (float*)d_out);
}

// round 8
// speedup vs baseline: 2.7628x; 1.4405x over previous
#include <cuda_runtime.h>
#include <math.h>

#define NLAYERS 4
#define DMODEL 1024
#define NHEADS 16
#define HDIM 64
#define FFDIM 4096
#define BATCH 2
#define SEQ 1024
#define MROWS (BATCH*SEQ)   // 2048

// ---------------- scratch (no allocations allowed) ----------------
__device__ float g_x [(size_t)MROWS*DMODEL];
__device__ float g_nb[(size_t)MROWS*DMODEL];
__device__ float g_qb[(size_t)MROWS*DMODEL];
__device__ float g_kb[(size_t)MROWS*DMODEL];
__device__ float g_vb[(size_t)MROWS*DMODEL];
__device__ float g_ab[(size_t)MROWS*DMODEL];
__device__ float g_sb[(size_t)BATCH*NHEADS*SEQ*SEQ];   // 128 MB scores
__device__ float g_t0b[(size_t)MROWS*FFDIM];
__device__ float g_t1b[(size_t)MROWS*FFDIM];
__device__ float g_biasb[NHEADS*SEQ];
__device__ float g_enct[(size_t)MROWS*DMODEL];
// tf32-rounded weights: 8 x (NL*D*D) + 2 x (NL*D*FF) + 1 x (NL*FF*D)
#define WD  ((size_t)NLAYERS*DMODEL*DMODEL)   // 4M floats
#define WF  ((size_t)NLAYERS*DMODEL*FFDIM)    // 16M floats
__device__ float g_wt[8*WD + 3*WF];

// ---------------- TF32 helpers ----------------
__device__ __forceinline__ float f2tf(float f) {
    unsigned u;
    asm("cvt.rna.tf32.f32 %0, %1;" : "=r"(u) : "f"(f));
    return __uint_as_float(u);
}

__device__ __forceinline__ void mma_tf32(
    float* d, const unsigned* a, const unsigned* b)
{
    asm volatile(
        "mma.sync.aligned.m16n8k8.row.col.f32.tf32.tf32.f32 "
        "{%0,%1,%2,%3}, {%4,%5,%6,%7}, {%8,%9}, {%0,%1,%2,%3};"
        : "+f"(d[0]), "+f"(d[1]), "+f"(d[2]), "+f"(d[3])
        : "r"(a[0]), "r"(a[1]), "r"(a[2]), "r"(a[3]),
          "r"(b[0]), "r"(b[1]));
}

// ---------------- small utility kernels ----------------
__global__ void copy4_k(const float* __restrict__ src, float* __restrict__ dst, int n4) {
    int i = blockIdx.x * blockDim.x + threadIdx.x;
    if (i < n4) ((float4*)dst)[i] = ((const float4*)src)[i];
}

// round-copy to tf32 format
__global__ void roundcpy_k(const float* __restrict__ src, float* __restrict__ dst, int n4) {
    int i = blockIdx.x * blockDim.x + threadIdx.x;
    if (i < n4) {
        float4 v = ((const float4*)src)[i];
        v.x = f2tf(v.x); v.y = f2tf(v.y); v.z = f2tf(v.z); v.w = f2tf(v.w);
        ((float4*)dst)[i] = v;
    }
}

// bias table: tab[h*SEQ + delta] = rel_emb[bucket(delta)][h], delta = max(i-j,0)
__global__ void biastab_k(const float* __restrict__ emb, float* __restrict__ tab) {
    int idx = blockIdx.x * blockDim.x + threadIdx.x;
    if (idx >= NHEADS * SEQ) return;
    int h = idx / SEQ;
    int d = idx % SEQ;
    int bucket;
    if (d < 16) {
        bucket = d;
    } else {
        float l = logf((float)d / 16.0f) / logf(8.0f) * 16.0f;
        bucket = 16 + (int)l;
        if (bucket > 31) bucket = 31;
    }
    tab[h * SEQ + d] = emb[bucket * NHEADS + h];
}

// RMSNorm: one block per row of 1024; optionally round output to tf32
__global__ __launch_bounds__(256) void rmsnorm_k(
    const float* __restrict__ x, const float* __restrict__ g, float* __restrict__ o,
    int roundOut)
{
    __shared__ float sh[32];
    const int row = blockIdx.x;
    const float* xr = x + (size_t)row * DMODEL;
    const int t = threadIdx.x;
    float s = 0.f;
    for (int c = t; c < DMODEL; c += 256) { float v = xr[c]; s += v * v; }
#pragma unroll
    for (int off = 16; off > 0; off >>= 1) s += __shfl_xor_sync(0xffffffffu, s, off);
    if ((t & 31) == 0) sh[t >> 5] = s;
    __syncthreads();
    if (t < 32) {
        float v = (t < 8) ? sh[t] : 0.f;
#pragma unroll
        for (int off = 4; off > 0; off >>= 1) v += __shfl_xor_sync(0xffffffffu, v, off);
        if (t == 0) sh[0] = v;
    }
    __syncthreads();
    const float r = rsqrtf(sh[0] / (float)DMODEL + 1e-6f);
    float* orow = o + (size_t)row * DMODEL;
    if (roundOut) {
        for (int c = t; c < DMODEL; c += 256) orow[c] = f2tf(g[c] * xr[c] * r);
    } else {
        for (int c = t; c < DMODEL; c += 256) orow[c] = g[c] * xr[c] * r;
    }
}

// ---------------- shared TF32 MMA core ----------------
// CTA tile 64 x NTILE, BK=16, 4 warps, warp tile 64 x (NTILE/4).
// A staged transposed [k][row] (stride 72); B staged [k][col] (stride NTILE+8).
// Inputs must already be tf32-rounded fp32. acc[4][NTILE/32][4].
template<int NTILE>
__device__ __forceinline__ void mm_core(
    const float* __restrict__ A, int lda,   // base at (row m0, k 0)
    const float* __restrict__ B, int ldb,   // base at (k 0, col n0)
    int K, float acc[4][NTILE/32][4])
{
    const int NT = NTILE / 32;
    __shared__ __align__(16) float As[2][16][72];
    __shared__ __align__(16) float Bs[2][16][NTILE + 8];
    const int t = threadIdx.x;
    const int lane = t & 31, warp = t >> 5;
    const int wn  = warp * (NTILE / 4);
    const int gid = lane >> 2, tig = lane & 3;

    const int aRow = t >> 1, aK = (t & 1) * 8;
    const float* Ap = A + (size_t)aRow * lda + aK;

    int bRow, bCol;
    if (NTILE == 128) { bRow = t >> 5; bCol = (t & 31) * 4; }
    else              { bRow = t >> 4; bCol = (t & 15) * 4; }
    const float* Bp = B + bCol;

    float4 a0, a1, bv0, bv1, bv2, bv3;
    // prologue
    a0 = *(const float4*)(Ap);
    a1 = *(const float4*)(Ap + 4);
    if (NTILE == 128) {
        bv0 = *(const float4*)(Bp + (size_t)(bRow     ) * ldb);
        bv1 = *(const float4*)(Bp + (size_t)(bRow +  4) * ldb);
        bv2 = *(const float4*)(Bp + (size_t)(bRow +  8) * ldb);
        bv3 = *(const float4*)(Bp + (size_t)(bRow + 12) * ldb);
    } else {
        bv0 = *(const float4*)(Bp + (size_t)(bRow    ) * ldb);
        bv1 = *(const float4*)(Bp + (size_t)(bRow + 8) * ldb);
    }
    {
        As[0][aK+0][aRow]=a0.x; As[0][aK+1][aRow]=a0.y;
        As[0][aK+2][aRow]=a0.z; As[0][aK+3][aRow]=a0.w;
        As[0][aK+4][aRow]=a1.x; As[0][aK+5][aRow]=a1.y;
        As[0][aK+6][aRow]=a1.z; As[0][aK+7][aRow]=a1.w;
        if (NTILE == 128) {
            *(float4*)&Bs[0][bRow   ][bCol] = bv0;
            *(float4*)&Bs[0][bRow+ 4][bCol] = bv1;
            *(float4*)&Bs[0][bRow+ 8][bCol] = bv2;
            *(float4*)&Bs[0][bRow+12][bCol] = bv3;
        } else {
            *(float4*)&Bs[0][bRow  ][bCol] = bv0;
            *(float4*)&Bs[0][bRow+8][bCol] = bv1;
        }
    }
    __syncthreads();

    int cur = 0;
    for (int k0 = 0; k0 < K; k0 += 16) {
        const bool last = (k0 + 16 >= K);
        if (!last) {
            a0 = *(const float4*)(Ap + k0 + 16);
            a1 = *(const float4*)(Ap + k0 + 20);
            const float* Bn = Bp + (size_t)(k0 + 16) * ldb;
            if (NTILE == 128) {
                bv0 = *(const float4*)(Bn + (size_t)(bRow     ) * ldb);
                bv1 = *(const float4*)(Bn + (size_t)(bRow +  4) * ldb);
                bv2 = *(const float4*)(Bn + (size_t)(bRow +  8) * ldb);
                bv3 = *(const float4*)(Bn + (size_t)(bRow + 12) * ldb);
            } else {
                bv0 = *(const float4*)(Bn + (size_t)(bRow    ) * ldb);
                bv1 = *(const float4*)(Bn + (size_t)(bRow + 8) * ldb);
            }
        }
#pragma unroll
        for (int ks = 0; ks < 2; ks++) {
            const int kk = ks * 8;
            unsigned af[4][4], bf[NT][2];
#pragma unroll
            for (int mt = 0; mt < 4; mt++) {
                const int r = mt * 16 + gid;
                af[mt][0] = __float_as_uint(As[cur][kk+tig  ][r]);
                af[mt][1] = __float_as_uint(As[cur][kk+tig  ][r+8]);
                af[mt][2] = __float_as_uint(As[cur][kk+tig+4][r]);
                af[mt][3] = __float_as_uint(As[cur][kk+tig+4][r+8]);
            }
#pragma unroll
            for (int nt = 0; nt < NT; nt++) {
                const int c = wn + nt * 8 + gid;
                bf[nt][0] = __float_as_uint(Bs[cur][kk+tig  ][c]);
                bf[nt][1] = __float_as_uint(Bs[cur][kk+tig+4][c]);
            }
#pragma unroll
            for (int mt = 0; mt < 4; mt++)
#pragma unroll
                for (int nt = 0; nt < NT; nt++)
                    mma_tf32(acc[mt][nt], af[mt], bf[nt]);
        }
        if (!last) {
            const int nxt = cur ^ 1;
            As[nxt][aK+0][aRow]=a0.x; As[nxt][aK+1][aRow]=a0.y;
            As[nxt][aK+2][aRow]=a0.z; As[nxt][aK+3][aRow]=a0.w;
            As[nxt][aK+4][aRow]=a1.x; As[nxt][aK+5][aRow]=a1.y;
            As[nxt][aK+6][aRow]=a1.z; As[nxt][aK+7][aRow]=a1.w;
            if (NTILE == 128) {
                *(float4*)&Bs[nxt][bRow   ][bCol] = bv0;
                *(float4*)&Bs[nxt][bRow+ 4][bCol] = bv1;
                *(float4*)&Bs[nxt][bRow+ 8][bCol] = bv2;
                *(float4*)&Bs[nxt][bRow+12][bCol] = bv3;
            } else {
                *(float4*)&Bs[nxt][bRow  ][bCol] = bv0;
                *(float4*)&Bs[nxt][bRow+8][bCol] = bv1;
            }
            __syncthreads();
            cur = nxt;
        }
    }
}

// ---------------- batched dense GEMM (up to 3 problems via z) ----------------
struct GB {
    const float* A[3];
    const float* B[3];
    const float* R[3];
    float*       C[3];
};

template<int NTILE>
__global__ __launch_bounds__(128) void mmT_k(
    GB gb, int N, int K, int lda, int ldb, int ldc, int roundOut)
{
    const int NT = NTILE / 32;
    const int z  = blockIdx.z;
    const int m0 = blockIdx.y * 64;
    const int n0 = blockIdx.x * NTILE;
    const float* A = gb.A[z] + (size_t)m0 * lda;
    const float* B = gb.B[z] + n0;
    float acc[4][NT][4];
#pragma unroll
    for (int i = 0; i < 4; i++)
#pragma unroll
        for (int j = 0; j < NT; j++)
#pragma unroll
            for (int r = 0; r < 4; r++) acc[i][j][r] = 0.f;

    mm_core<NTILE>(A, lda, B, ldb, K, acc);

    const int t = threadIdx.x, lane = t & 31, warp = t >> 5;
    const int gid = lane >> 2, tig = lane & 3;
    const int wn = warp * (NTILE / 4);
    const float* R = gb.R[z];
    float* C = gb.C[z];
#pragma unroll
    for (int mt = 0; mt < 4; mt++) {
        const int r = m0 + mt * 16 + gid;
#pragma unroll
        for (int nt = 0; nt < NT; nt++) {
            const int c = n0 + wn + nt * 8 + 2 * tig;
            const size_t o0 = (size_t)r * ldc + c;
            const size_t o1 = (size_t)(r + 8) * ldc + c;
            float v0 = acc[mt][nt][0], v1 = acc[mt][nt][1];
            float v2 = acc[mt][nt][2], v3 = acc[mt][nt][3];
            if (R) { v0 += R[o0]; v1 += R[o0+1]; v2 += R[o1]; v3 += R[o1+1]; }
            if (roundOut) { v0=f2tf(v0); v1=f2tf(v1); v2=f2tf(v2); v3=f2tf(v3); }
            C[o0] = v0; C[o0+1] = v1; C[o1] = v2; C[o1+1] = v3;
        }
    }
}

// ---------------- attention scores (TF32 MMA): S = Q K^T + bias + mask ------
// tile 64(i) x 128(j), K=64, inputs pre-rounded. grid (SEQ/128, SEQ/64, B*H)
__global__ __launch_bounds__(128) void scores_tc_k(
    const float* __restrict__ Q, const float* __restrict__ Kv,
    float* __restrict__ S, const float* __restrict__ biasTab,
    const float* __restrict__ mask, int selfMode)
{
    __shared__ __align__(16) float As[2][16][72];
    __shared__ __align__(16) float Bs[2][16][136];
    const int bh = blockIdx.z;
    const int b  = bh >> 4, h = bh & 15;
    const int i0 = blockIdx.y * 64;
    const int j0 = blockIdx.x * 128;
    const int t  = threadIdx.x;
    const int lane = t & 31, warp = t >> 5;
    const int wn  = warp * 32;
    const int gid = lane >> 2, tig = lane & 3;

    const int aRow = t >> 1, aK = (t & 1) * 8;
    const float* Ap = Q + (size_t)(b * SEQ + i0 + aRow) * DMODEL + h * HDIM + aK;
    const float* Bp = Kv + (size_t)(b * SEQ + j0 + t) * DMODEL + h * HDIM;

    float4 a0, a1, k0v, k1v, k2v, k3v;
    a0  = *(const float4*)(Ap);
    a1  = *(const float4*)(Ap + 4);
    k0v = *(const float4*)(Bp);
    k1v = *(const float4*)(Bp + 4);
    k2v = *(const float4*)(Bp + 8);
    k3v = *(const float4*)(Bp + 12);
    {
        As[0][aK+0][aRow]=a0.x; As[0][aK+1][aRow]=a0.y;
        As[0][aK+2][aRow]=a0.z; As[0][aK+3][aRow]=a0.w;
        As[0][aK+4][aRow]=a1.x; As[0][aK+5][aRow]=a1.y;
        As[0][aK+6][aRow]=a1.z; As[0][aK+7][aRow]=a1.w;
        Bs[0][ 0][t]=k0v.x; Bs[0][ 1][t]=k0v.y; Bs[0][ 2][t]=k0v.z; Bs[0][ 3][t]=k0v.w;
        Bs[0][ 4][t]=k1v.x; Bs[0][ 5][t]=k1v.y; Bs[0][ 6][t]=k1v.z; Bs[0][ 7][t]=k1v.w;
        Bs[0][ 8][t]=k2v.x; Bs[0][ 9][t]=k2v.y; Bs[0][10][t]=k2v.z; Bs[0][11][t]=k2v.w;
        Bs[0][12][t]=k3v.x; Bs[0][13][t]=k3v.y; Bs[0][14][t]=k3v.z; Bs[0][15][t]=k3v.w;
    }
    __syncthreads();

    float acc[4][4][4];
#pragma unroll
    for (int i = 0; i < 4; i++)
#pragma unroll
        for (int j = 0; j < 4; j++)
#pragma unroll
            for (int r = 0; r < 4; r++) acc[i][j][r] = 0.f;

    int cur = 0;
    for (int kb = 0; kb < HDIM; kb += 16) {
        const bool last = (kb + 16 >= HDIM);
        if (!last) {
            a0  = *(const float4*)(Ap + kb + 16);
            a1  = *(const float4*)(Ap + kb + 20);
            k0v = *(const float4*)(Bp + kb + 16);
            k1v = *(const float4*)(Bp + kb + 20);
            k2v = *(const float4*)(Bp + kb + 24);
            k3v = *(const float4*)(Bp + kb + 28);
        }
#pragma unroll
        for (int ks = 0; ks < 2; ks++) {
            const int kk = ks * 8;
            unsigned af[4][4], bf[4][2];
#pragma unroll
            for (int mt = 0; mt < 4; mt++) {
                const int r = mt * 16 + gid;
                af[mt][0] = __float_as_uint(As[cur][kk+tig  ][r]);
                af[mt][1] = __float_as_uint(As[cur][kk+tig  ][r+8]);
                af[mt][2] = __float_as_uint(As[cur][kk+tig+4][r]);
                af[mt][3] = __float_as_uint(As[cur][kk+tig+4][r+8]);
            }
#pragma unroll
            for (int nt = 0; nt < 4; nt++) {
                const int c = wn + nt * 8 + gid;
                bf[nt][0] = __float_as_uint(Bs[cur][kk+tig  ][c]);
                bf[nt][1] = __float_as_uint(Bs[cur][kk+tig+4][c]);
            }
#pragma unroll
            for (int mt = 0; mt < 4; mt++)
#pragma unroll
                for (int nt = 0; nt < 4; nt++)
                    mma_tf32(acc[mt][nt], af[mt], bf[nt]);
        }
        if (!last) {
            const int nxt = cur ^ 1;
            As[nxt][aK+0][aRow]=a0.x; As[nxt][aK+1][aRow]=a0.y;
            As[nxt][aK+2][aRow]=a0.z; As[nxt][aK+3][aRow]=a0.w;
            As[nxt][aK+4][aRow]=a1.x; As[nxt][aK+5][aRow]=a1.y;
            As[nxt][aK+6][aRow]=a1.z; As[nxt][aK+7][aRow]=a1.w;
            Bs[nxt][ 0][t]=k0v.x; Bs[nxt][ 1][t]=k0v.y; Bs[nxt][ 2][t]=k0v.z; Bs[nxt][ 3][t]=k0v.w;
            Bs[nxt][ 4][t]=k1v.x; Bs[nxt][ 5][t]=k1v.y; Bs[nxt][ 6][t]=k1v.z; Bs[nxt][ 7][t]=k1v.w;
            Bs[nxt][ 8][t]=k2v.x; Bs[nxt][ 9][t]=k2v.y; Bs[nxt][10][t]=k2v.z; Bs[nxt][11][t]=k2v.w;
            Bs[nxt][12][t]=k3v.x; Bs[nxt][13][t]=k3v.y; Bs[nxt][14][t]=k3v.z; Bs[nxt][15][t]=k3v.w;
            __syncthreads();
            cur = nxt;
        }
    }

    // epilogue: bias + mask + store
#pragma unroll
    for (int mt = 0; mt < 4; mt++) {
#pragma unroll
        for (int nt = 0; nt < 4; nt++) {
            const int c = j0 + wn + nt * 8 + 2 * tig;
#pragma unroll
            for (int half = 0; half < 2; half++) {
                const int gi = i0 + mt * 16 + gid + half * 8;
                const size_t srow = ((size_t)bh * SEQ + gi) * SEQ;
#pragma unroll
                for (int cc = 0; cc < 2; cc++) {
                    const int gj = c + cc;
                    float v = acc[mt][nt][half * 2 + cc];
                    if (selfMode) {
                        int dd = gi - gj; if (dd < 0) dd = 0;
                        v += biasTab[h * SEQ + dd]
                           + mask[(size_t)b * SEQ * SEQ + (size_t)gi * SEQ + gj];
                    } else {
                        v += mask[(size_t)b * SEQ + gj];
                    }
                    S[srow + gj] = v;
                }
            }
        }
    }
}

// ---------------- O = P @ V (TF32 MMA), P,V pre-rounded --------------------
// tile 64(i) x 64(hd), K=SEQ. grid (1, SEQ/64, B*H)
__global__ __launch_bounds__(128) void av_tc_k(
    const float* __restrict__ S, const float* __restrict__ V, float* __restrict__ O)
{
    const int bh = blockIdx.z;
    const int b  = bh >> 4, h = bh & 15;
    const int i0 = blockIdx.y * 64;
    const float* A = S + ((size_t)bh * SEQ + i0) * SEQ;
    const float* B = V + (size_t)b * SEQ * DMODEL + h * HDIM;
    float acc[4][2][4];
#pragma unroll
    for (int i = 0; i < 4; i++)
#pragma unroll
        for (int j = 0; j < 2; j++)
#pragma unroll
            for (int r = 0; r < 4; r++) acc[i][j][r] = 0.f;

    mm_core<64>(A, SEQ, B, DMODEL, SEQ, acc);

    const int t = threadIdx.x, lane = t & 31, warp = t >> 5;
    const int gid = lane >> 2, tig = lane & 3;
    const int wn = warp * 16;
#pragma unroll
    for (int mt = 0; mt < 4; mt++) {
        const int r = i0 + mt * 16 + gid;
#pragma unroll
        for (int nt = 0; nt < 2; nt++) {
            const int c = wn + nt * 8 + 2 * tig;
            const size_t o0 = (size_t)(b * SEQ + r    ) * DMODEL + h * HDIM + c;
            const size_t o1 = (size_t)(b * SEQ + r + 8) * DMODEL + h * HDIM + c;
            O[o0]   = f2tf(acc[mt][nt][0]);
            O[o0+1] = f2tf(acc[mt][nt][1]);
            O[o1]   = f2tf(acc[mt][nt][2]);
            O[o1+1] = f2tf(acc[mt][nt][3]);
        }
    }
}

// ---------------- row softmax over 1024 cols; output rounded to tf32 -------
__global__ __launch_bounds__(256) void softmax_k(float* __restrict__ S)
{
    __shared__ float sh[32];
    const size_t row = blockIdx.x;
    float* p = S + row * SEQ;
    const int t = threadIdx.x;
    float v[4];
    float mx = -3.4e38f;
#pragma unroll
    for (int u = 0; u < 4; u++) { v[u] = p[t + u * 256]; mx = fmaxf(mx, v[u]); }
#pragma unroll
    for (int off = 16; off > 0; off >>= 1) mx = fmaxf(mx, __shfl_xor_sync(0xffffffffu, mx, off));
    if ((t & 31) == 0) sh[t >> 5] = mx;
    __syncthreads();
    if (t < 32) {
        float m2 = (t < 8) ? sh[t] : -3.4e38f;
#pragma unroll
        for (int off = 4; off > 0; off >>= 1) m2 = fmaxf(m2, __shfl_xor_sync(0xffffffffu, m2, off));
        if (t == 0) sh[0] = m2;
    }
    __syncthreads();
    const float mxa = sh[0];
    __syncthreads();
    float s = 0.f;
#pragma unroll
    for (int u = 0; u < 4; u++) { v[u] = expf(v[u] - mxa); s += v[u]; }
#pragma unroll
    for (int off = 16; off > 0; off >>= 1) s += __shfl_xor_sync(0xffffffffu, s, off);
    if ((t & 31) == 0) sh[t >> 5] = s;
    __syncthreads();
    if (t < 32) {
        float s2 = (t < 8) ? sh[t] : 0.f;
#pragma unroll
        for (int off = 4; off > 0; off >>= 1) s2 += __shfl_xor_sync(0xffffffffu, s2, off);
        if (t == 0) sh[0] = s2;
    }
    __syncthreads();
    const float inv = 1.0f / sh[0];
#pragma unroll
    for (int u = 0; u < 4; u++) p[t + u * 256] = f2tf(v[u] * inv);
}

// ---------------- GeGLU combine: t0 = tf32(gelu_exact(t0) * t1) ------------
__global__ void geglu_k(float* __restrict__ t0, const float* __restrict__ t1, int n) {
    int i = blockIdx.x * blockDim.x + threadIdx.x;
    if (i < n) {
        float x = t0[i];
        float g = 0.5f * x * (1.0f + erff(x * 0.70710678118654752f));
        t0[i] = f2tf(g * t1[i]);
    }
}

// ---------------- host orchestration ----------------
extern "C" void kernel_launch(void* const* d_in, const int* in_sizes, int n_in,
                              void* d_out, int out_size)
{
    const float* hs    = (const float*)d_in[0];
    const float* enc   = (const float*)d_in[1];
    const float* amask = (const float*)d_in[2];
    const float* emask = (const float*)d_in[3];
    const float* Win[11] = {
        (const float*)d_in[4],  (const float*)d_in[5],  (const float*)d_in[6],
        (const float*)d_in[7],  (const float*)d_in[8],  (const float*)d_in[9],
        (const float*)d_in[10], (const float*)d_in[11], (const float*)d_in[12],
        (const float*)d_in[13], (const float*)d_in[14]
    };
    const float* g1    = (const float*)d_in[15];
    const float* g2    = (const float*)d_in[16];
    const float* g3    = (const float*)d_in[17];
    const float* gf    = (const float*)d_in[18];
    const float* remb  = (const float*)d_in[19];

    static float *px = nullptr, *pn, *pq, *pk, *pv, *pa, *ps, *pt0, *pt1, *pb,
                 *pet, *pw;
    if (!px) {
        cudaGetSymbolAddress((void**)&px,  g_x);
        cudaGetSymbolAddress((void**)&pn,  g_nb);
        cudaGetSymbolAddress((void**)&pq,  g_qb);
        cudaGetSymbolAddress((void**)&pk,  g_kb);
        cudaGetSymbolAddress((void**)&pv,  g_vb);
        cudaGetSymbolAddress((void**)&pa,  g_ab);
        cudaGetSymbolAddress((void**)&ps,  g_sb);
        cudaGetSymbolAddress((void**)&pt0, g_t0b);
        cudaGetSymbolAddress((void**)&pt1, g_t1b);
        cudaGetSymbolAddress((void**)&pb,  g_biasb);
        cudaGetSymbolAddress((void**)&pet, g_enct);
        cudaGetSymbolAddress((void**)&pw,  g_wt);
    }

    // tf32-rounded weight copies (offsets in floats)
    float* W[11];
    {
        size_t off = 0;
        for (int i = 0; i < 8; i++) { W[i] = pw + off; off += WD; }
        W[8] = pw + off; off += WF;      // Wi0
        W[9] = pw + off; off += WF;      // Wi1
        W[10] = pw + off;                // Wof
    }
    for (int i = 0; i < 8; i++)
        roundcpy_k<<<(int)(WD/4 + 255)/256, 256>>>(Win[i], W[i], (int)(WD/4));
    for (int i = 8; i < 11; i++)
        roundcpy_k<<<(int)(WF/4 + 255)/256, 256>>>(Win[i], W[i], (int)(WF/4));

    copy4_k<<<(MROWS * DMODEL / 4 + 255) / 256, 256>>>(hs, px, MROWS * DMODEL / 4);
    roundcpy_k<<<(MROWS * DMODEL / 4 + 255) / 256, 256>>>(enc, pet, MROWS * DMODEL / 4);
    biastab_k<<<(NHEADS * SEQ + 255) / 256, 256>>>(remb, pb);

    const dim3 gD3(DMODEL / 128, MROWS / 64, 3);   // batched QKV
    const dim3 gD1(DMODEL / 128, MROWS / 64, 1);   // single D-GEMM
    const dim3 gF2(FFDIM / 128,  MROWS / 64, 2);   // batched Wi0/Wi1
    const dim3 gS(SEQ / 128, SEQ / 64, BATCH * NHEADS);
    const dim3 gA(1, SEQ / 64, BATCH * NHEADS);
    const int softmaxBlocks = BATCH * NHEADS * SEQ;

    for (int i = 0; i < NLAYERS; i++) {
        const size_t oD = (size_t)i * DMODEL * DMODEL;
        const size_t oF = (size_t)i * DMODEL * FFDIM;
        // --- causal self-attention with rel-pos bias ---
        rmsnorm_k<<<MROWS, 256>>>(px, g1 + i * DMODEL, pn, 1);
        {
            GB gb = {};
            gb.A[0] = pn; gb.A[1] = pn; gb.A[2] = pn;
            gb.B[0] = W[0] + oD; gb.B[1] = W[1] + oD; gb.B[2] = W[2] + oD;
            gb.C[0] = pq; gb.C[1] = pk; gb.C[2] = pv;
            mmT_k<128><<<gD3, 128>>>(gb, DMODEL, DMODEL, DMODEL, DMODEL, DMODEL, 1);
        }
        scores_tc_k<<<gS, 128>>>(pq, pk, ps, pb, amask, 1);
        softmax_k<<<softmaxBlocks, 256>>>(ps);
        av_tc_k<<<gA, 128>>>(ps, pv, pa);
        {
            GB gb = {};
            gb.A[0] = pa; gb.B[0] = W[3] + oD; gb.R[0] = px; gb.C[0] = px;
            mmT_k<128><<<gD1, 128>>>(gb, DMODEL, DMODEL, DMODEL, DMODEL, DMODEL, 0);
        }
        // --- cross-attention ---
        rmsnorm_k<<<MROWS, 256>>>(px, g2 + i * DMODEL, pn, 1);
        {
            GB gb = {};
            gb.A[0] = pn; gb.A[1] = pet; gb.A[2] = pet;
            gb.B[0] = W[4] + oD; gb.B[1] = W[5] + oD; gb.B[2] = W[6] + oD;
            gb.C[0] = pq; gb.C[1] = pk; gb.C[2] = pv;
            mmT_k<128><<<gD3, 128>>>(gb, DMODEL, DMODEL, DMODEL, DMODEL, DMODEL, 1);
        }
        scores_tc_k<<<gS, 128>>>(pq, pk, ps, pb, emask, 0);
        softmax_k<<<softmaxBlocks, 256>>>(ps);
        av_tc_k<<<gA, 128>>>(ps, pv, pa);
        {
            GB gb = {};
            gb.A[0] = pa; gb.B[0] = W[7] + oD; gb.R[0] = px; gb.C[0] = px;
            mmT_k<128><<<gD1, 128>>>(gb, DMODEL, DMODEL, DMODEL, DMODEL, DMODEL, 0);
        }
        // --- GeGLU FFN ---
        rmsnorm_k<<<MROWS, 256>>>(px, g3 + i * DMODEL, pn, 1);
        {
            GB gb = {};
            gb.A[0] = pn; gb.A[1] = pn;
            gb.B[0] = W[8] + oF; gb.B[1] = W[9] + oF;
            gb.C[0] = pt0; gb.C[1] = pt1;
            mmT_k<128><<<gF2, 128>>>(gb, FFDIM, DMODEL, DMODEL, FFDIM, FFDIM, 0);
        }
        geglu_k<<<(MROWS * FFDIM + 255) / 256, 256>>>(pt0, pt1, MROWS * FFDIM);
        {
            GB gb = {};
            gb.A[0] = pt0; gb.B[0] = W[10] + (size_t)i * FFDIM * DMODEL;
            gb.R[0] = px; gb.C[0] = px;
            mmT_k<128><<<gD1, 128>>>(gb, DMODEL, FFDIM, FFDIM, DMODEL, DMODEL, 0);
        }
    }
    rmsnorm_k<<<MROWS, 256>>>(px, gf, (float*)d_out, 0);
}

// round 9
// speedup vs baseline: 3.0046x; 1.0875x over previous
#include <cuda_runtime.h>
#include <math.h>

#define NLAYERS 4
#define DMODEL 1024
#define NHEADS 16
#define HDIM 64
#define FFDIM 4096
#define BATCH 2
#define SEQ 1024
#define MROWS (BATCH*SEQ)   // 2048

// ---------------- scratch (no allocations allowed) ----------------
__device__ float g_x [(size_t)MROWS*DMODEL];
__device__ float g_nb[(size_t)MROWS*DMODEL];
__device__ float g_qb[(size_t)MROWS*DMODEL];
__device__ float g_kb[(size_t)MROWS*DMODEL];
__device__ float g_vb[(size_t)MROWS*DMODEL];
__device__ float g_ab[(size_t)MROWS*DMODEL];
__device__ float g_t0b[(size_t)MROWS*FFDIM];
__device__ float g_t1b[(size_t)MROWS*FFDIM];
__device__ float g_biasb[NHEADS*SEQ];

// ---------------- TF32 helpers ----------------
__device__ __forceinline__ float f2tf(float f) {
    unsigned u;
    asm("cvt.rna.tf32.f32 %0, %1;" : "=r"(u) : "f"(f));
    return __uint_as_float(u);
}

__device__ __forceinline__ void mma_tf32(
    float* d, const unsigned* a, const unsigned* b)
{
    asm volatile(
        "mma.sync.aligned.m16n8k8.row.col.f32.tf32.tf32.f32 "
        "{%0,%1,%2,%3}, {%4,%5,%6,%7}, {%8,%9}, {%0,%1,%2,%3};"
        : "+f"(d[0]), "+f"(d[1]), "+f"(d[2]), "+f"(d[3])
        : "r"(a[0]), "r"(a[1]), "r"(a[2]), "r"(a[3]),
          "r"(b[0]), "r"(b[1]));
}

// ---------------- small utility kernels ----------------
__global__ void copy4_k(const float* __restrict__ src, float* __restrict__ dst, int n4) {
    int i = blockIdx.x * blockDim.x + threadIdx.x;
    if (i < n4) ((float4*)dst)[i] = ((const float4*)src)[i];
}

// bias table: tab[h*SEQ + delta] = rel_emb[bucket(delta)][h], delta = max(i-j,0)
__global__ void biastab_k(const float* __restrict__ emb, float* __restrict__ tab) {
    int idx = blockIdx.x * blockDim.x + threadIdx.x;
    if (idx >= NHEADS * SEQ) return;
    int h = idx / SEQ;
    int d = idx % SEQ;
    int bucket;
    if (d < 16) {
        bucket = d;
    } else {
        float l = logf((float)d / 16.0f) / logf(8.0f) * 16.0f;
        bucket = 16 + (int)l;
        if (bucket > 31) bucket = 31;
    }
    tab[h * SEQ + d] = emb[bucket * NHEADS + h];
}

// RMSNorm: one block per row of 1024
__global__ __launch_bounds__(256) void rmsnorm_k(
    const float* __restrict__ x, const float* __restrict__ g, float* __restrict__ o)
{
    __shared__ float sh[32];
    const int row = blockIdx.x;
    const float* xr = x + (size_t)row * DMODEL;
    const int t = threadIdx.x;
    float s = 0.f;
    for (int c = t; c < DMODEL; c += 256) { float v = xr[c]; s += v * v; }
#pragma unroll
    for (int off = 16; off > 0; off >>= 1) s += __shfl_xor_sync(0xffffffffu, s, off);
    if ((t & 31) == 0) sh[t >> 5] = s;
    __syncthreads();
    if (t < 32) {
        float v = (t < 8) ? sh[t] : 0.f;
#pragma unroll
        for (int off = 4; off > 0; off >>= 1) v += __shfl_xor_sync(0xffffffffu, v, off);
        if (t == 0) sh[0] = v;
    }
    __syncthreads();
    const float r = rsqrtf(sh[0] / (float)DMODEL + 1e-6f);
    float* orow = o + (size_t)row * DMODEL;
    for (int c = t; c < DMODEL; c += 256) orow[c] = g[c] * xr[c] * r;
}

// ---------------- TF32 MMA GEMM core (rounds inputs at staging) ----------------
// CTA tile 64 x 128, BK=16, 4 warps, warp tile 64 x 32.
// A staged transposed [k][row] (stride 72); B staged [k][col] (stride 136).
__device__ __forceinline__ void mm_core128(
    const float* __restrict__ A, int lda,
    const float* __restrict__ B, int ldb,
    int K, float acc[4][4][4])
{
    __shared__ __align__(16) float As[2][16][72];
    __shared__ __align__(16) float Bs[2][16][136];
    const int t = threadIdx.x;
    const int lane = t & 31, warp = t >> 5;
    const int wn  = warp * 32;
    const int gid = lane >> 2, tig = lane & 3;

    const int aRow = t >> 1, aK = (t & 1) * 8;
    const float* Ap = A + (size_t)aRow * lda + aK;
    const int bRow = t >> 5, bCol = (t & 31) * 4;
    const float* Bp = B + bCol;

    float4 a0, a1, bv0, bv1, bv2, bv3;
    a0 = *(const float4*)(Ap);
    a1 = *(const float4*)(Ap + 4);
    bv0 = *(const float4*)(Bp + (size_t)(bRow     ) * ldb);
    bv1 = *(const float4*)(Bp + (size_t)(bRow +  4) * ldb);
    bv2 = *(const float4*)(Bp + (size_t)(bRow +  8) * ldb);
    bv3 = *(const float4*)(Bp + (size_t)(bRow + 12) * ldb);
    {
        As[0][aK+0][aRow]=f2tf(a0.x); As[0][aK+1][aRow]=f2tf(a0.y);
        As[0][aK+2][aRow]=f2tf(a0.z); As[0][aK+3][aRow]=f2tf(a0.w);
        As[0][aK+4][aRow]=f2tf(a1.x); As[0][aK+5][aRow]=f2tf(a1.y);
        As[0][aK+6][aRow]=f2tf(a1.z); As[0][aK+7][aRow]=f2tf(a1.w);
        float4 c0 = make_float4(f2tf(bv0.x),f2tf(bv0.y),f2tf(bv0.z),f2tf(bv0.w));
        float4 c1 = make_float4(f2tf(bv1.x),f2tf(bv1.y),f2tf(bv1.z),f2tf(bv1.w));
        float4 c2 = make_float4(f2tf(bv2.x),f2tf(bv2.y),f2tf(bv2.z),f2tf(bv2.w));
        float4 c3 = make_float4(f2tf(bv3.x),f2tf(bv3.y),f2tf(bv3.z),f2tf(bv3.w));
        *(float4*)&Bs[0][bRow   ][bCol] = c0;
        *(float4*)&Bs[0][bRow+ 4][bCol] = c1;
        *(float4*)&Bs[0][bRow+ 8][bCol] = c2;
        *(float4*)&Bs[0][bRow+12][bCol] = c3;
    }
    __syncthreads();

    int cur = 0;
    for (int k0 = 0; k0 < K; k0 += 16) {
        const bool last = (k0 + 16 >= K);
        if (!last) {
            a0 = *(const float4*)(Ap + k0 + 16);
            a1 = *(const float4*)(Ap + k0 + 20);
            const float* Bn = Bp + (size_t)(k0 + 16) * ldb;
            bv0 = *(const float4*)(Bn + (size_t)(bRow     ) * ldb);
            bv1 = *(const float4*)(Bn + (size_t)(bRow +  4) * ldb);
            bv2 = *(const float4*)(Bn + (size_t)(bRow +  8) * ldb);
            bv3 = *(const float4*)(Bn + (size_t)(bRow + 12) * ldb);
        }
#pragma unroll
        for (int ks = 0; ks < 2; ks++) {
            const int kk = ks * 8;
            unsigned af[4][4], bf[4][2];
#pragma unroll
            for (int mt = 0; mt < 4; mt++) {
                const int r = mt * 16 + gid;
                af[mt][0] = __float_as_uint(As[cur][kk+tig  ][r]);
                af[mt][1] = __float_as_uint(As[cur][kk+tig  ][r+8]);
                af[mt][2] = __float_as_uint(As[cur][kk+tig+4][r]);
                af[mt][3] = __float_as_uint(As[cur][kk+tig+4][r+8]);
            }
#pragma unroll
            for (int nt = 0; nt < 4; nt++) {
                const int c = wn + nt * 8 + gid;
                bf[nt][0] = __float_as_uint(Bs[cur][kk+tig  ][c]);
                bf[nt][1] = __float_as_uint(Bs[cur][kk+tig+4][c]);
            }
#pragma unroll
            for (int mt = 0; mt < 4; mt++)
#pragma unroll
                for (int nt = 0; nt < 4; nt++)
                    mma_tf32(acc[mt][nt], af[mt], bf[nt]);
        }
        if (!last) {
            const int nxt = cur ^ 1;
            As[nxt][aK+0][aRow]=f2tf(a0.x); As[nxt][aK+1][aRow]=f2tf(a0.y);
            As[nxt][aK+2][aRow]=f2tf(a0.z); As[nxt][aK+3][aRow]=f2tf(a0.w);
            As[nxt][aK+4][aRow]=f2tf(a1.x); As[nxt][aK+5][aRow]=f2tf(a1.y);
            As[nxt][aK+6][aRow]=f2tf(a1.z); As[nxt][aK+7][aRow]=f2tf(a1.w);
            float4 c0 = make_float4(f2tf(bv0.x),f2tf(bv0.y),f2tf(bv0.z),f2tf(bv0.w));
            float4 c1 = make_float4(f2tf(bv1.x),f2tf(bv1.y),f2tf(bv1.z),f2tf(bv1.w));
            float4 c2 = make_float4(f2tf(bv2.x),f2tf(bv2.y),f2tf(bv2.z),f2tf(bv2.w));
            float4 c3 = make_float4(f2tf(bv3.x),f2tf(bv3.y),f2tf(bv3.z),f2tf(bv3.w));
            *(float4*)&Bs[nxt][bRow   ][bCol] = c0;
            *(float4*)&Bs[nxt][bRow+ 4][bCol] = c1;
            *(float4*)&Bs[nxt][bRow+ 8][bCol] = c2;
            *(float4*)&Bs[nxt][bRow+12][bCol] = c3;
            __syncthreads();
            cur = nxt;
        }
    }
}

// ---------------- batched dense GEMM (up to 3 problems via z) ----------------
struct GB {
    const float* A[3];
    const float* B[3];
    const float* R[3];
    float*       C[3];
};

__global__ __launch_bounds__(128) void mmT_k(
    GB gb, int N, int K, int lda, int ldb, int ldc)
{
    const int z  = blockIdx.z;
    const int m0 = blockIdx.y * 64;
    const int n0 = blockIdx.x * 128;
    const float* A = gb.A[z] + (size_t)m0 * lda;
    const float* B = gb.B[z] + n0;
    float acc[4][4][4];
#pragma unroll
    for (int i = 0; i < 4; i++)
#pragma unroll
        for (int j = 0; j < 4; j++)
#pragma unroll
            for (int r = 0; r < 4; r++) acc[i][j][r] = 0.f;

    mm_core128(A, lda, B, ldb, K, acc);

    const int t = threadIdx.x, lane = t & 31, warp = t >> 5;
    const int gid = lane >> 2, tig = lane & 3;
    const int wn = warp * 32;
    const float* R = gb.R[z];
    float* C = gb.C[z];
#pragma unroll
    for (int mt = 0; mt < 4; mt++) {
        const int r = m0 + mt * 16 + gid;
#pragma unroll
        for (int nt = 0; nt < 4; nt++) {
            const int c = n0 + wn + nt * 8 + 2 * tig;
            const size_t o0 = (size_t)r * ldc + c;
            const size_t o1 = (size_t)(r + 8) * ldc + c;
            float v0 = acc[mt][nt][0], v1 = acc[mt][nt][1];
            float v2 = acc[mt][nt][2], v3 = acc[mt][nt][3];
            if (R) { v0 += R[o0]; v1 += R[o0+1]; v2 += R[o1]; v3 += R[o1+1]; }
            C[o0] = v0; C[o0+1] = v1; C[o1] = v2; C[o1+1] = v3;
        }
    }
}

// ---------------- flash attention ----------------
// grid (1, SEQ/64, B*H), block 128 (4 warps).
// S-phase: warps M-split (16 rows each, all 64 cols) -> row stats intra-warp.
// PV-phase: warps N-split (16 dims each), P via smem transpose.
// Self mode: j-tiles beyond diagonal skipped (masked entries exp to exactly 0).
__global__ __launch_bounds__(128) void flash_k(
    const float* __restrict__ Q, const float* __restrict__ Kv,
    const float* __restrict__ V, float* __restrict__ O,
    const float* __restrict__ biasTab, const float* __restrict__ mask,
    int selfMode)
{
    __shared__ __align__(16) float KV[64][72];
    __shared__ __align__(16) float Ps[64][72];
    __shared__ float sscale[64];
    __shared__ float sl[64];

    const int bh = blockIdx.z, b = bh >> 4, h = bh & 15;
    const int i0 = blockIdx.y * 64;
    const int t = threadIdx.x, lane = t & 31, warp = t >> 5;
    const int gid = lane >> 2, tig = lane & 3;
    const int wr = warp * 16;            // S-phase row base
    const int wn = warp * 16;            // PV-phase dim base
    const int sr = t >> 1, sc = (t & 1) * 32;  // staging coords

    // Q fragments for rows wr+gid / wr+gid+8, k = 0..63 (one-time gather)
    unsigned aq[8][4];
    {
        const float* q0 = Q + (size_t)(b * SEQ + i0 + wr + gid) * DMODEL + h * HDIM;
        const float* q1 = q0 + 8 * DMODEL;
#pragma unroll
        for (int k8 = 0; k8 < 8; k8++) {
            const int k = k8 * 8;
            aq[k8][0] = __float_as_uint(f2tf(q0[k + tig]));
            aq[k8][1] = __float_as_uint(f2tf(q1[k + tig]));
            aq[k8][2] = __float_as_uint(f2tf(q0[k + tig + 4]));
            aq[k8][3] = __float_as_uint(f2tf(q1[k + tig + 4]));
        }
    }

    float m_run[2] = {-3.0e38f, -3.0e38f};
    float l_run[2] = {0.f, 0.f};
    float acc_o[4][2][4];
#pragma unroll
    for (int mt = 0; mt < 4; mt++)
#pragma unroll
        for (int nt = 0; nt < 2; nt++)
#pragma unroll
            for (int e = 0; e < 4; e++) acc_o[mt][nt][e] = 0.f;

    const float* kbase = Kv + (size_t)b * SEQ * DMODEL + h * HDIM;
    const float* vbase = V  + (size_t)b * SEQ * DMODEL + h * HDIM;
    const int nj = selfMode ? (i0 / 64 + 1) : (SEQ / 64);

    for (int jt = 0; jt < nj; jt++) {
        const int j0 = jt * 64;
        __syncthreads();                       // KV free of prior-iter readers
        // stage K -> KV[dim][j]
        {
            const float* kp = kbase + (size_t)(j0 + sr) * DMODEL + sc;
#pragma unroll
            for (int u = 0; u < 8; u++) {
                float4 v4 = *(const float4*)(kp + u * 4);
                KV[sc+u*4+0][sr] = f2tf(v4.x);
                KV[sc+u*4+1][sr] = f2tf(v4.y);
                KV[sc+u*4+2][sr] = f2tf(v4.z);
                KV[sc+u*4+3][sr] = f2tf(v4.w);
            }
        }
        __syncthreads();
        // S = Q K^T : rows wr..wr+15, cols 0..63
        float s[8][4];
#pragma unroll
        for (int nt = 0; nt < 8; nt++)
#pragma unroll
            for (int e = 0; e < 4; e++) s[nt][e] = 0.f;
#pragma unroll
        for (int k8 = 0; k8 < 8; k8++) {
            const int k = k8 * 8;
            unsigned bf[8][2];
#pragma unroll
            for (int nt = 0; nt < 8; nt++) {
                bf[nt][0] = __float_as_uint(KV[k+tig  ][nt*8+gid]);
                bf[nt][1] = __float_as_uint(KV[k+tig+4][nt*8+gid]);
            }
#pragma unroll
            for (int nt = 0; nt < 8; nt++)
                mma_tf32(s[nt], aq[k8], bf[nt]);
        }
        // bias + mask + row stats
        float pm[2] = {-3.0e38f, -3.0e38f};
        const int gi0 = i0 + wr + gid;
#pragma unroll
        for (int nt = 0; nt < 8; nt++) {
#pragma unroll
            for (int e = 0; e < 4; e++) {
                const int gi = gi0 + (e >> 1) * 8;
                const int gj = j0 + nt * 8 + 2 * tig + (e & 1);
                float v = s[nt][e];
                if (selfMode) {
                    int dd = gi - gj; if (dd < 0) dd = 0;
                    v += biasTab[h * SEQ + dd]
                       + mask[(size_t)b * SEQ * SEQ + (size_t)gi * SEQ + gj];
                } else {
                    v += mask[(size_t)b * SEQ + gj];
                }
                s[nt][e] = v;
                pm[e >> 1] = fmaxf(pm[e >> 1], v);
            }
        }
#pragma unroll
        for (int i = 0; i < 2; i++) {
            pm[i] = fmaxf(pm[i], __shfl_xor_sync(0xffffffffu, pm[i], 1));
            pm[i] = fmaxf(pm[i], __shfl_xor_sync(0xffffffffu, pm[i], 2));
        }
        float mnew[2], scl[2], psum[2] = {0.f, 0.f};
#pragma unroll
        for (int i = 0; i < 2; i++) {
            mnew[i] = fmaxf(m_run[i], pm[i]);
            scl[i]  = __expf(m_run[i] - mnew[i]);
        }
#pragma unroll
        for (int nt = 0; nt < 8; nt++)
#pragma unroll
            for (int e = 0; e < 4; e++) {
                float p = __expf(s[nt][e] - mnew[e >> 1]);
                s[nt][e] = p;
                psum[e >> 1] += p;
            }
#pragma unroll
        for (int i = 0; i < 2; i++) {
            psum[i] += __shfl_xor_sync(0xffffffffu, psum[i], 1);
            psum[i] += __shfl_xor_sync(0xffffffffu, psum[i], 2);
            l_run[i] = l_run[i] * scl[i] + psum[i];
            m_run[i] = mnew[i];
        }
        if (tig == 0) {
            sscale[wr + gid]     = scl[0];
            sscale[wr + gid + 8] = scl[1];
        }
        // store P transposed [j][i], tf32-rounded
#pragma unroll
        for (int nt = 0; nt < 8; nt++)
#pragma unroll
            for (int e = 0; e < 4; e++)
                Ps[nt*8 + 2*tig + (e & 1)][wr + gid + (e >> 1) * 8] = f2tf(s[nt][e]);
        __syncthreads();                       // Ps + sscale visible; K reads done
        // stage V -> KV[j][dim]
        {
            const float* vp = vbase + (size_t)(j0 + sr) * DMODEL + sc;
#pragma unroll
            for (int u = 0; u < 8; u++) {
                float4 v4 = *(const float4*)(vp + u * 4);
                v4.x = f2tf(v4.x); v4.y = f2tf(v4.y);
                v4.z = f2tf(v4.z); v4.w = f2tf(v4.w);
                *(float4*)&KV[sr][sc + u * 4] = v4;
            }
        }
        // rescale acc_o by this tile's per-row factors
        float rs[4][2];
#pragma unroll
        for (int mt = 0; mt < 4; mt++) {
            rs[mt][0] = sscale[mt * 16 + gid];
            rs[mt][1] = sscale[mt * 16 + gid + 8];
        }
#pragma unroll
        for (int mt = 0; mt < 4; mt++)
#pragma unroll
            for (int nt = 0; nt < 2; nt++)
#pragma unroll
                for (int e = 0; e < 4; e++)
                    acc_o[mt][nt][e] *= rs[mt][e >> 1];
        __syncthreads();                       // V staged
        // O += P V
#pragma unroll
        for (int k8 = 0; k8 < 8; k8++) {
            const int k = k8 * 8;
            unsigned af[4][4], bf[2][2];
#pragma unroll
            for (int mt = 0; mt < 4; mt++) {
                af[mt][0] = __float_as_uint(Ps[k+tig  ][mt*16+gid]);
                af[mt][1] = __float_as_uint(Ps[k+tig  ][mt*16+gid+8]);
                af[mt][2] = __float_as_uint(Ps[k+tig+4][mt*16+gid]);
                af[mt][3] = __float_as_uint(Ps[k+tig+4][mt*16+gid+8]);
            }
#pragma unroll
            for (int nt = 0; nt < 2; nt++) {
                bf[nt][0] = __float_as_uint(KV[k+tig  ][wn+nt*8+gid]);
                bf[nt][1] = __float_as_uint(KV[k+tig+4][wn+nt*8+gid]);
            }
#pragma unroll
            for (int mt = 0; mt < 4; mt++)
#pragma unroll
                for (int nt = 0; nt < 2; nt++)
                    mma_tf32(acc_o[mt][nt], af[mt], bf[nt]);
        }
    }
    // final: O = acc / l
    if (tig == 0) {
        sl[wr + gid]     = l_run[0];
        sl[wr + gid + 8] = l_run[1];
    }
    __syncthreads();
#pragma unroll
    for (int mt = 0; mt < 4; mt++) {
        const float inv0 = 1.0f / sl[mt * 16 + gid];
        const float inv1 = 1.0f / sl[mt * 16 + gid + 8];
        const int r0 = i0 + mt * 16 + gid;
#pragma unroll
        for (int nt = 0; nt < 2; nt++) {
            const int c = h * HDIM + wn + nt * 8 + 2 * tig;
            const size_t o0 = (size_t)(b * SEQ + r0) * DMODEL + c;
            const size_t o1 = o0 + (size_t)8 * DMODEL;
            O[o0]     = acc_o[mt][nt][0] * inv0;
            O[o0 + 1] = acc_o[mt][nt][1] * inv0;
            O[o1]     = acc_o[mt][nt][2] * inv1;
            O[o1 + 1] = acc_o[mt][nt][3] * inv1;
        }
    }
}

// ---------------- GeGLU combine: t0 = gelu_exact(t0) * t1 ------------------
__global__ void geglu_k(float* __restrict__ t0, const float* __restrict__ t1, int n) {
    int i = blockIdx.x * blockDim.x + threadIdx.x;
    if (i < n) {
        float x = t0[i];
        float g = 0.5f * x * (1.0f + erff(x * 0.70710678118654752f));
        t0[i] = g * t1[i];
    }
}

// ---------------- host orchestration ----------------
extern "C" void kernel_launch(void* const* d_in, const int* in_sizes, int n_in,
                              void* d_out, int out_size)
{
    const float* hs    = (const float*)d_in[0];
    const float* enc   = (const float*)d_in[1];
    const float* amask = (const float*)d_in[2];
    const float* emask = (const float*)d_in[3];
    const float* Wq_s  = (const float*)d_in[4];
    const float* Wk_s  = (const float*)d_in[5];
    const float* Wv_s  = (const float*)d_in[6];
    const float* Wo_s  = (const float*)d_in[7];
    const float* Wq_c  = (const float*)d_in[8];
    const float* Wk_c  = (const float*)d_in[9];
    const float* Wv_c  = (const float*)d_in[10];
    const float* Wo_c  = (const float*)d_in[11];
    const float* Wi0   = (const float*)d_in[12];
    const float* Wi1   = (const float*)d_in[13];
    const float* Wof   = (const float*)d_in[14];
    const float* g1    = (const float*)d_in[15];
    const float* g2    = (const float*)d_in[16];
    const float* g3    = (const float*)d_in[17];
    const float* gf    = (const float*)d_in[18];
    const float* remb  = (const float*)d_in[19];

    static float *px = nullptr, *pn, *pq, *pk, *pv, *pa, *pt0, *pt1, *pb;
    if (!px) {
        cudaGetSymbolAddress((void**)&px,  g_x);
        cudaGetSymbolAddress((void**)&pn,  g_nb);
        cudaGetSymbolAddress((void**)&pq,  g_qb);
        cudaGetSymbolAddress((void**)&pk,  g_kb);
        cudaGetSymbolAddress((void**)&pv,  g_vb);
        cudaGetSymbolAddress((void**)&pa,  g_ab);
        cudaGetSymbolAddress((void**)&pt0, g_t0b);
        cudaGetSymbolAddress((void**)&pt1, g_t1b);
        cudaGetSymbolAddress((void**)&pb,  g_biasb);
    }

    const dim3 gD3(DMODEL / 128, MROWS / 64, 3);   // batched QKV
    const dim3 gD1(DMODEL / 128, MROWS / 64, 1);   // single D-GEMM
    const dim3 gF2(FFDIM / 128,  MROWS / 64, 2);   // batched Wi0/Wi1
    const dim3 gFl(1, SEQ / 64, BATCH * NHEADS);   // flash attention

    copy4_k<<<(MROWS * DMODEL / 4 + 255) / 256, 256>>>(hs, px, MROWS * DMODEL / 4);
    biastab_k<<<(NHEADS * SEQ + 255) / 256, 256>>>(remb, pb);

    for (int i = 0; i < NLAYERS; i++) {
        const size_t oD = (size_t)i * DMODEL * DMODEL;
        const size_t oF = (size_t)i * DMODEL * FFDIM;
        // --- causal self-attention with rel-pos bias ---
        rmsnorm_k<<<MROWS, 256>>>(px, g1 + i * DMODEL, pn);
        {
            GB gb = {};
            gb.A[0] = pn; gb.A[1] = pn; gb.A[2] = pn;
            gb.B[0] = Wq_s + oD; gb.B[1] = Wk_s + oD; gb.B[2] = Wv_s + oD;
            gb.C[0] = pq; gb.C[1] = pk; gb.C[2] = pv;
            mmT_k<<<gD3, 128>>>(gb, DMODEL, DMODEL, DMODEL, DMODEL, DMODEL);
        }
        flash_k<<<gFl, 128>>>(pq, pk, pv, pa, pb, amask, 1);
        {
            GB gb = {};
            gb.A[0] = pa; gb.B[0] = Wo_s + oD; gb.R[0] = px; gb.C[0] = px;
            mmT_k<<<gD1, 128>>>(gb, DMODEL, DMODEL, DMODEL, DMODEL, DMODEL);
        }
        // --- cross-attention ---
        rmsnorm_k<<<MROWS, 256>>>(px, g2 + i * DMODEL, pn);
        {
            GB gb = {};
            gb.A[0] = pn; gb.A[1] = enc; gb.A[2] = enc;
            gb.B[0] = Wq_c + oD; gb.B[1] = Wk_c + oD; gb.B[2] = Wv_c + oD;
            gb.C[0] = pq; gb.C[1] = pk; gb.C[2] = pv;
            mmT_k<<<gD3, 128>>>(gb, DMODEL, DMODEL, DMODEL, DMODEL, DMODEL);
        }
        flash_k<<<gFl, 128>>>(pq, pk, pv, pa, pb, emask, 0);
        {
            GB gb = {};
            gb.A[0] = pa; gb.B[0] = Wo_c + oD; gb.R[0] = px; gb.C[0] = px;
            mmT_k<<<gD1, 128>>>(gb, DMODEL, DMODEL, DMODEL, DMODEL, DMODEL);
        }
        // --- GeGLU FFN ---
        rmsnorm_k<<<MROWS, 256>>>(px, g3 + i * DMODEL, pn);
        {
            GB gb = {};
            gb.A[0] = pn; gb.A[1] = pn;
            gb.B[0] = Wi0 + oF; gb.B[1] = Wi1 + oF;
            gb.C[0] = pt0; gb.C[1] = pt1;
            mmT_k<<<gF2, 128>>>(gb, FFDIM, DMODEL, DMODEL, FFDIM, FFDIM);
        }
        geglu_k<<<(MROWS * FFDIM + 255) / 256, 256>>>(pt0, pt1, MROWS * FFDIM);
        {
            GB gb = {};
            gb.A[0] = pt0; gb.B[0] = Wof + (size_t)i * FFDIM * DMODEL;
            gb.R[0] = px; gb.C[0] = px;
            mmT_k<<<gD1, 128>>>(gb, DMODEL, FFDIM, FFDIM, DMODEL, DMODEL);
        }
    }
    rmsnorm_k<<<MROWS, 256>>>(px, gf, (float*)d_out);
}